// round 5
// baseline (speedup 1.0000x reference)
#include <cuda_runtime.h>
#include <math.h>

#define NB 4
#define SEQ 2048
#define DM 1024
#define DH 128
#define CHUNK 8                 // kv tiles (of 64) per attention CTA
#define NQT (SEQ / 64)          // 32 q-tiles
#define CPB 80                  // chunks per batch = 8*(1+2+3+4)
typedef unsigned int U32;

// Scratch (device globals: allocation-free rule)
__device__ float g_q[NB * SEQ * DH];
__device__ float g_k[NB * SEQ * DH];
__device__ float g_v[NB * SEQ * DH];
__device__ float g_ctx[NB * SEQ * DH];
// split-KV partials: [b][qt][kc][64 rows][128] + per-row m,l
__device__ float g_pO[NB * NQT * 4 * 64 * DH];
__device__ float g_pm[NB * NQT * 4 * 64];
__device__ float g_pl[NB * NQT * 4 * 64];

// ---------------------------------------------------------------------------
__device__ __forceinline__ U32 f2tf(float f) {
    U32 u;
    asm("cvt.rna.tf32.f32 %0, %1;" : "=r"(u) : "f"(f));
    return u;
}
__device__ __forceinline__ void mma8(float* c, const U32* a, const U32* b) {
    asm volatile(
        "mma.sync.aligned.m16n8k8.row.col.f32.tf32.tf32.f32 "
        "{%0,%1,%2,%3}, {%4,%5,%6,%7}, {%8,%9}, {%0,%1,%2,%3};\n"
        : "+f"(c[0]), "+f"(c[1]), "+f"(c[2]), "+f"(c[3])
        : "r"(a[0]), "r"(a[1]), "r"(a[2]), "r"(a[3]),
          "r"(b[0]), "r"(b[1]));
}
__device__ __forceinline__ void cpa(U32 saddr, const float* g) {
    asm volatile("cp.async.ca.shared.global [%0], [%1], 16;\n"
                 :: "r"(saddr), "l"(g));
}
#define CP_COMMIT asm volatile("cp.async.commit_group;\n" ::: "memory")
#define CP_WAIT(n) asm volatile("cp.async.wait_group %0;\n" :: "n"(n) : "memory")

// ---------------------------------------------------------------------------
// Kernel 1: QKV projection, tf32 TC, cp.async 2-stage smem double buffer.
// grid=(128,3), 256 thr; CTA 64x128, BK=32; warps 2x4 (warp tile 32x32).
// Stage: Xs[64*36] + Ws[32*136] fp32; convert to tf32 at fragment load.
// ---------------------------------------------------------------------------
#define G_STAGE_X (64 * 36)
#define G_STAGE_W (32 * 136)
#define G_STAGE   (G_STAGE_X + G_STAGE_W)
#define G_SMEM_BYTES (2 * G_STAGE * 4)

__global__ __launch_bounds__(256) void qkv_tc(
    const float* __restrict__ x,
    const float* __restrict__ wq,
    const float* __restrict__ wk,
    const float* __restrict__ wv)
{
    extern __shared__ float sm[];
    const U32 sb = (U32)__cvta_generic_to_shared(sm);

    const int tid = threadIdx.x;
    const int lane = tid & 31;
    const int wid = tid >> 5;
    const int wm = wid >> 2;
    const int wn = wid & 3;
    const int m0 = blockIdx.x * 64;
    const int lr = lane >> 2;
    const int lc = lane & 3;

    const float* w;
    float* o;
    if (blockIdx.y == 0)      { w = wq; o = g_q; }
    else if (blockIdx.y == 1) { w = wk; o = g_k; }
    else                      { w = wv; o = g_v; }

    const int xr_r = tid >> 3, xr_c = (tid & 7) * 4;   // X 64x32: 2 f4/thr
    const int wr_k = tid >> 5, wr_c = (tid & 31) * 4;  // W 32x128: 4 f4/thr

    // prologue: stage 0
    {
        U32 xs = sb, ws = sb + G_STAGE_X * 4;
        cpa(xs + (U32)(xr_r * 36 + xr_c) * 4,        x + (size_t)(m0 + xr_r) * DM + xr_c);
        cpa(xs + (U32)((xr_r + 32) * 36 + xr_c) * 4, x + (size_t)(m0 + xr_r + 32) * DM + xr_c);
        #pragma unroll
        for (int i = 0; i < 4; i++)
            cpa(ws + (U32)((wr_k + i * 8) * 136 + wr_c) * 4,
                w + (size_t)(wr_k + i * 8) * DH + wr_c);
    }
    CP_COMMIT;

    float acc[2][4][4];
    #pragma unroll
    for (int mt = 0; mt < 2; mt++)
        #pragma unroll
        for (int nt = 0; nt < 4; nt++)
            #pragma unroll
            for (int j = 0; j < 4; j++) acc[mt][nt][j] = 0.f;

    for (int it = 0; it < DM / 32; it++) {
        const int s = it & 1;
        const float* Xs = sm + s * G_STAGE;
        const float* Ws = Xs + G_STAGE_X;

        CP_WAIT(0);
        __syncthreads();

        // stream next stage while MMAs run
        if (it + 1 < DM / 32) {
            const int k0n = (it + 1) * 32;
            U32 xs = sb + (U32)((1 - s) * G_STAGE) * 4;
            U32 ws = xs + G_STAGE_X * 4;
            cpa(xs + (U32)(xr_r * 36 + xr_c) * 4,        x + (size_t)(m0 + xr_r) * DM + k0n + xr_c);
            cpa(xs + (U32)((xr_r + 32) * 36 + xr_c) * 4, x + (size_t)(m0 + xr_r + 32) * DM + k0n + xr_c);
            #pragma unroll
            for (int i = 0; i < 4; i++)
                cpa(ws + (U32)((wr_k + i * 8) * 136 + wr_c) * 4,
                    w + (size_t)(k0n + wr_k + i * 8) * DH + wr_c);
        }
        CP_COMMIT;

        #pragma unroll
        for (int q8 = 0; q8 < 4; q8++) {
            int kb = q8 * 8;
            U32 a[2][4], b[4][2];
            #pragma unroll
            for (int mt = 0; mt < 2; mt++) {
                int r = wm * 32 + mt * 16 + lr;
                a[mt][0] = f2tf(Xs[r * 36 + kb + lc]);
                a[mt][1] = f2tf(Xs[(r + 8) * 36 + kb + lc]);
                a[mt][2] = f2tf(Xs[r * 36 + kb + lc + 4]);
                a[mt][3] = f2tf(Xs[(r + 8) * 36 + kb + lc + 4]);
            }
            #pragma unroll
            for (int nt = 0; nt < 4; nt++) {
                int n = wn * 32 + nt * 8 + lr;
                b[nt][0] = f2tf(Ws[(kb + lc) * 136 + n]);
                b[nt][1] = f2tf(Ws[(kb + lc + 4) * 136 + n]);
            }
            #pragma unroll
            for (int mt = 0; mt < 2; mt++)
                #pragma unroll
                for (int nt = 0; nt < 4; nt++)
                    mma8(acc[mt][nt], a[mt], b[nt]);
        }
    }

    #pragma unroll
    for (int mt = 0; mt < 2; mt++)
        #pragma unroll
        for (int nt = 0; nt < 4; nt++) {
            int r = m0 + wm * 32 + mt * 16 + lr;
            int cc = wn * 32 + nt * 8 + 2 * lc;
            *(float2*)(o + (size_t)r * DH + cc) =
                make_float2(acc[mt][nt][0], acc[mt][nt][1]);
            *(float2*)(o + (size_t)(r + 8) * DH + cc) =
                make_float2(acc[mt][nt][2], acc[mt][nt][3]);
        }
}

// ---------------------------------------------------------------------------
// Kernel 2: split-KV causal flash attention, cp.async pipelined.
// grid=(80,4), 128 thr. Separate K/V buffers; P passed via shuffles (no Ps).
// Smem fp32: Qs[64*132] Ks[64*132] Vs[64*136] = 102400 B -> 2 CTA/SM.
// ---------------------------------------------------------------------------
#define ATTN_SMEM_BYTES ((64 * 132 + 64 * 132 + 64 * 136) * 4)

__global__ __launch_bounds__(128) void attn_tc()
{
    extern __shared__ float sm[];
    float* Qs = sm;                      // stride 132
    float* Ks = sm + 64 * 132;           // stride 132
    float* Vs = sm + 2 * 64 * 132;       // stride 136
    const U32 sb = (U32)__cvta_generic_to_shared(sm);
    const U32 qb = sb;
    const U32 kbb = sb + 64 * 132 * 4;
    const U32 vbb = sb + 2 * 64 * 132 * 4;

    const int tid = threadIdx.x;
    const int lane = tid & 31;
    const int wid = tid >> 5;
    const int lr = lane >> 2;
    const int lc = lane & 3;
    const int b = blockIdx.y;
    const float scale = 0.088388347648318447f;   // 1/sqrt(128)

    // map blockIdx.x -> (q-tile, kv-chunk)
    int c = blockIdx.x, qt = 0, start = 0;
    for (;;) {
        int n = qt / 8 + 1;
        if (c < start + n) break;
        start += n;
        qt++;
    }
    const int kc = c - start;
    const int kt0 = kc * CHUNK;
    const int kt1 = min(kt0 + CHUNK, qt + 1);
    const int q0 = qt * 64;

    const float* qg = g_q + (size_t)b * SEQ * DH;
    const float* kg = g_k + (size_t)b * SEQ * DH;
    const float* vg = g_v + (size_t)b * SEQ * DH;

    // prologue: Q + K(kt0) as group0, V(kt0) as group1
    #pragma unroll
    for (int i = 0; i < 16; i++) {
        int idx = tid + i * 128;
        int r = idx >> 5, c4 = (idx & 31) * 4;
        cpa(qb + (U32)(r * 132 + c4) * 4, qg + (size_t)(q0 + r) * DH + c4);
    }
    {
        const int k0row = kt0 * 64;
        #pragma unroll
        for (int i = 0; i < 16; i++) {
            int idx = tid + i * 128;
            int r = idx >> 5, c4 = (idx & 31) * 4;
            cpa(kbb + (U32)(r * 132 + c4) * 4, kg + (size_t)(k0row + r) * DH + c4);
        }
    }
    CP_COMMIT;
    {
        const int k0row = kt0 * 64;
        #pragma unroll
        for (int i = 0; i < 16; i++) {
            int idx = tid + i * 128;
            int r = idx >> 5, c4 = (idx & 31) * 4;
            cpa(vbb + (U32)(r * 136 + c4) * 4, vg + (size_t)(k0row + r) * DH + c4);
        }
    }
    CP_COMMIT;

    float m0v = -1e30f, m1v = -1e30f, l0 = 0.f, l1 = 0.f;
    float O[16][4];
    #pragma unroll
    for (int nt = 0; nt < 16; nt++)
        #pragma unroll
        for (int j = 0; j < 4; j++) O[nt][j] = 0.f;

    const int rloc = wid * 16 + lr;
    const int src0 = (lr << 2) | (lc >> 1);
    const int src1 = src0 + 2;
    const bool hi = lc & 1;

    for (int t = kt0; t < kt1; t++) {
        CP_WAIT(1);                      // Q + K_t arrived (V_t may be in flight)
        __syncthreads();

        // S = Q @ K^T
        float sc[8][4];
        #pragma unroll
        for (int nt = 0; nt < 8; nt++)
            #pragma unroll
            for (int j = 0; j < 4; j++) sc[nt][j] = 0.f;

        #pragma unroll
        for (int k8 = 0; k8 < 16; k8++) {
            int kb = k8 * 8;
            U32 a[4];
            a[0] = f2tf(Qs[rloc * 132 + kb + lc]);
            a[1] = f2tf(Qs[(rloc + 8) * 132 + kb + lc]);
            a[2] = f2tf(Qs[rloc * 132 + kb + lc + 4]);
            a[3] = f2tf(Qs[(rloc + 8) * 132 + kb + lc + 4]);
            #pragma unroll
            for (int nt = 0; nt < 8; nt++) {
                U32 bb[2];
                int n = nt * 8 + lr;
                bb[0] = f2tf(Ks[n * 132 + kb + lc]);
                bb[1] = f2tf(Ks[n * 132 + kb + lc + 4]);
                mma8(sc[nt], a, bb);
            }
        }

        __syncthreads();                 // all warps done reading Ks
        // stream K_{t+1} during softmax + PV
        if (t + 1 < kt1) {
            const int k0n = (t + 1) * 64;
            #pragma unroll
            for (int i = 0; i < 16; i++) {
                int idx = tid + i * 128;
                int r = idx >> 5, c4 = (idx & 31) * 4;
                cpa(kbb + (U32)(r * 132 + c4) * 4, kg + (size_t)(k0n + r) * DH + c4);
            }
        }
        CP_COMMIT;

        // scale, causal mask, online softmax
        #pragma unroll
        for (int nt = 0; nt < 8; nt++)
            #pragma unroll
            for (int j = 0; j < 4; j++) sc[nt][j] *= scale;

        if (t == qt) {
            #pragma unroll
            for (int nt = 0; nt < 8; nt++) {
                int c0 = nt * 8 + 2 * lc;
                if (c0 > rloc)         sc[nt][0] = -1e30f;
                if (c0 + 1 > rloc)     sc[nt][1] = -1e30f;
                if (c0 > rloc + 8)     sc[nt][2] = -1e30f;
                if (c0 + 1 > rloc + 8) sc[nt][3] = -1e30f;
            }
        }

        float mx0 = -1e30f, mx1 = -1e30f;
        #pragma unroll
        for (int nt = 0; nt < 8; nt++) {
            mx0 = fmaxf(mx0, fmaxf(sc[nt][0], sc[nt][1]));
            mx1 = fmaxf(mx1, fmaxf(sc[nt][2], sc[nt][3]));
        }
        mx0 = fmaxf(mx0, __shfl_xor_sync(0xffffffffu, mx0, 1));
        mx0 = fmaxf(mx0, __shfl_xor_sync(0xffffffffu, mx0, 2));
        mx1 = fmaxf(mx1, __shfl_xor_sync(0xffffffffu, mx1, 1));
        mx1 = fmaxf(mx1, __shfl_xor_sync(0xffffffffu, mx1, 2));

        float mn0 = fmaxf(m0v, mx0), mn1 = fmaxf(m1v, mx1);
        float cr0 = __expf(m0v - mn0), cr1 = __expf(m1v - mn1);
        m0v = mn0; m1v = mn1;

        float s0 = 0.f, s1 = 0.f;
        #pragma unroll
        for (int nt = 0; nt < 8; nt++) {
            sc[nt][0] = __expf(sc[nt][0] - mn0);
            sc[nt][1] = __expf(sc[nt][1] - mn0);
            sc[nt][2] = __expf(sc[nt][2] - mn1);
            sc[nt][3] = __expf(sc[nt][3] - mn1);
            s0 += sc[nt][0] + sc[nt][1];
            s1 += sc[nt][2] + sc[nt][3];
        }
        s0 += __shfl_xor_sync(0xffffffffu, s0, 1);
        s0 += __shfl_xor_sync(0xffffffffu, s0, 2);
        s1 += __shfl_xor_sync(0xffffffffu, s1, 1);
        s1 += __shfl_xor_sync(0xffffffffu, s1, 2);
        l0 = l0 * cr0 + s0;
        l1 = l1 * cr1 + s1;

        #pragma unroll
        for (int nt = 0; nt < 16; nt++) {
            O[nt][0] *= cr0; O[nt][1] *= cr0;
            O[nt][2] *= cr1; O[nt][3] *= cr1;
        }

        CP_WAIT(1);                      // V_t ready (K_{t+1} still streaming)
        __syncthreads();

        // O += P @ V ; P A-frags reconstructed from C-layout via shuffles
        #pragma unroll
        for (int k8 = 0; k8 < 8; k8++) {
            float v00 = __shfl_sync(0xffffffffu, sc[k8][0], src0);
            float v01 = __shfl_sync(0xffffffffu, sc[k8][1], src0);
            float v10 = __shfl_sync(0xffffffffu, sc[k8][2], src0);
            float v11 = __shfl_sync(0xffffffffu, sc[k8][3], src0);
            float w00 = __shfl_sync(0xffffffffu, sc[k8][0], src1);
            float w01 = __shfl_sync(0xffffffffu, sc[k8][1], src1);
            float w10 = __shfl_sync(0xffffffffu, sc[k8][2], src1);
            float w11 = __shfl_sync(0xffffffffu, sc[k8][3], src1);
            U32 a[4];
            a[0] = f2tf(hi ? v01 : v00);
            a[1] = f2tf(hi ? v11 : v10);
            a[2] = f2tf(hi ? w01 : w00);
            a[3] = f2tf(hi ? w11 : w10);

            int kb = k8 * 8;
            #pragma unroll
            for (int nt = 0; nt < 16; nt++) {
                U32 bb[2];
                int n = nt * 8 + lr;
                bb[0] = f2tf(Vs[(kb + lc) * 136 + n]);
                bb[1] = f2tf(Vs[(kb + lc + 4) * 136 + n]);
                mma8(O[nt], a, bb);
            }
        }

        __syncthreads();                 // all warps done reading Vs
        if (t + 1 < kt1) {
            const int k0n = (t + 1) * 64;
            #pragma unroll
            for (int i = 0; i < 16; i++) {
                int idx = tid + i * 128;
                int r = idx >> 5, c4 = (idx & 31) * 4;
                cpa(vbb + (U32)(r * 136 + c4) * 4, vg + (size_t)(k0n + r) * DH + c4);
            }
        }
        CP_COMMIT;
    }

    // write partials
    const size_t pbase = (size_t)((b * NQT + qt) * 4 + kc);
    float* pO = g_pO + pbase * 64 * DH;
    #pragma unroll
    for (int nt = 0; nt < 16; nt++) {
        int cc = nt * 8 + 2 * lc;
        *(float2*)&pO[rloc * DH + cc]       = make_float2(O[nt][0], O[nt][1]);
        *(float2*)&pO[(rloc + 8) * DH + cc] = make_float2(O[nt][2], O[nt][3]);
    }
    if (lc == 0) {
        g_pm[pbase * 64 + rloc]     = m0v;
        g_pl[pbase * 64 + rloc]     = l0;
        g_pm[pbase * 64 + rloc + 8] = m1v;
        g_pl[pbase * 64 + rloc + 8] = l1;
    }
}

// ---------------------------------------------------------------------------
// Kernel 2b: combine split-KV partials -> g_ctx. grid=(32,4), 256 thr.
// ---------------------------------------------------------------------------
__global__ __launch_bounds__(256) void attn_combine()
{
    const int qt = blockIdx.x, b = blockIdx.y;
    const int nc = qt / 8 + 1;
    const int row = threadIdx.x >> 2;
    const int cs = (threadIdx.x & 3) * 32;
    const size_t pb = (size_t)(b * NQT + qt) * 4;

    float m[4], l[4], w[4];
    float M = -1e30f;
    #pragma unroll 4
    for (int i = 0; i < nc; i++) {
        m[i] = g_pm[(pb + i) * 64 + row];
        l[i] = g_pl[(pb + i) * 64 + row];
        M = fmaxf(M, m[i]);
    }
    float L = 0.f;
    #pragma unroll 4
    for (int i = 0; i < nc; i++) {
        w[i] = __expf(m[i] - M);
        L += w[i] * l[i];
    }
    const float inv = 1.f / L;

    float acc[32];
    #pragma unroll
    for (int j = 0; j < 32; j++) acc[j] = 0.f;

    #pragma unroll 4
    for (int i = 0; i < nc; i++) {
        const float* p = g_pO + (pb + i) * 64 * DH + (size_t)row * DH + cs;
        float wi = w[i];
        #pragma unroll
        for (int j = 0; j < 8; j++) {
            float4 v = *(const float4*)(p + j * 4);
            acc[j * 4 + 0] += wi * v.x;
            acc[j * 4 + 1] += wi * v.y;
            acc[j * 4 + 2] += wi * v.z;
            acc[j * 4 + 3] += wi * v.w;
        }
    }

    float* cg = g_ctx + ((size_t)b * SEQ + qt * 64 + row) * DH + cs;
    #pragma unroll
    for (int j = 0; j < 8; j++)
        *(float4*)(cg + j * 4) = make_float4(acc[j * 4] * inv, acc[j * 4 + 1] * inv,
                                             acc[j * 4 + 2] * inv, acc[j * 4 + 3] * inv);
}

// ---------------------------------------------------------------------------
// Kernel 3: output projection, cp.async 2-stage. grid=(128,8), 256 thr.
// ---------------------------------------------------------------------------
__global__ __launch_bounds__(256) void proj_tc(
    const float* __restrict__ wo, float* __restrict__ out)
{
    extern __shared__ float sm[];
    const U32 sb = (U32)__cvta_generic_to_shared(sm);

    const int tid = threadIdx.x;
    const int lane = tid & 31;
    const int wid = tid >> 5;
    const int wm = wid >> 2;
    const int wn = wid & 3;
    const int m0 = blockIdx.x * 64;
    const int n0 = blockIdx.y * 128;
    const int lr = lane >> 2;
    const int lc = lane & 3;

    const int xr_r = tid >> 3, xr_c = (tid & 7) * 4;
    const int wr_k = tid >> 5, wr_c = (tid & 31) * 4;

    {
        U32 xs = sb, ws = sb + G_STAGE_X * 4;
        cpa(xs + (U32)(xr_r * 36 + xr_c) * 4,        g_ctx + (size_t)(m0 + xr_r) * DH + xr_c);
        cpa(xs + (U32)((xr_r + 32) * 36 + xr_c) * 4, g_ctx + (size_t)(m0 + xr_r + 32) * DH + xr_c);
        #pragma unroll
        for (int i = 0; i < 4; i++)
            cpa(ws + (U32)((wr_k + i * 8) * 136 + wr_c) * 4,
                wo + (size_t)(wr_k + i * 8) * DM + n0 + wr_c);
    }
    CP_COMMIT;

    float acc[2][4][4];
    #pragma unroll
    for (int mt = 0; mt < 2; mt++)
        #pragma unroll
        for (int nt = 0; nt < 4; nt++)
            #pragma unroll
            for (int j = 0; j < 4; j++) acc[mt][nt][j] = 0.f;

    for (int it = 0; it < DH / 32; it++) {
        const int s = it & 1;
        const float* Xs = sm + s * G_STAGE;
        const float* Ws = Xs + G_STAGE_X;

        CP_WAIT(0);
        __syncthreads();

        if (it + 1 < DH / 32) {
            const int k0n = (it + 1) * 32;
            U32 xs = sb + (U32)((1 - s) * G_STAGE) * 4;
            U32 ws = xs + G_STAGE_X * 4;
            cpa(xs + (U32)(xr_r * 36 + xr_c) * 4,        g_ctx + (size_t)(m0 + xr_r) * DH + k0n + xr_c);
            cpa(xs + (U32)((xr_r + 32) * 36 + xr_c) * 4, g_ctx + (size_t)(m0 + xr_r + 32) * DH + k0n + xr_c);
            #pragma unroll
            for (int i = 0; i < 4; i++)
                cpa(ws + (U32)((wr_k + i * 8) * 136 + wr_c) * 4,
                    wo + (size_t)(k0n + wr_k + i * 8) * DM + n0 + wr_c);
        }
        CP_COMMIT;

        #pragma unroll
        for (int q8 = 0; q8 < 4; q8++) {
            int kb = q8 * 8;
            U32 a[2][4], b[4][2];
            #pragma unroll
            for (int mt = 0; mt < 2; mt++) {
                int r = wm * 32 + mt * 16 + lr;
                a[mt][0] = f2tf(Xs[r * 36 + kb + lc]);
                a[mt][1] = f2tf(Xs[(r + 8) * 36 + kb + lc]);
                a[mt][2] = f2tf(Xs[r * 36 + kb + lc + 4]);
                a[mt][3] = f2tf(Xs[(r + 8) * 36 + kb + lc + 4]);
            }
            #pragma unroll
            for (int nt = 0; nt < 4; nt++) {
                int n = wn * 32 + nt * 8 + lr;
                b[nt][0] = f2tf(Ws[(kb + lc) * 136 + n]);
                b[nt][1] = f2tf(Ws[(kb + lc + 4) * 136 + n]);
            }
            #pragma unroll
            for (int mt = 0; mt < 2; mt++)
                #pragma unroll
                for (int nt = 0; nt < 4; nt++)
                    mma8(acc[mt][nt], a[mt], b[nt]);
        }
    }

    #pragma unroll
    for (int mt = 0; mt < 2; mt++)
        #pragma unroll
        for (int nt = 0; nt < 4; nt++) {
            int r = m0 + wm * 32 + mt * 16 + lr;
            int cc = n0 + wn * 32 + nt * 8 + 2 * lc;
            *(float2*)(out + (size_t)r * DM + cc) =
                make_float2(acc[mt][nt][0], acc[mt][nt][1]);
            *(float2*)(out + (size_t)(r + 8) * DM + cc) =
                make_float2(acc[mt][nt][2], acc[mt][nt][3]);
        }
}

// ---------------------------------------------------------------------------
extern "C" void kernel_launch(void* const* d_in, const int* in_sizes, int n_in,
                              void* d_out, int out_size)
{
    const float* x  = (const float*)d_in[0];
    const float* wq = (const float*)d_in[1];
    const float* wk = (const float*)d_in[2];
    const float* wv = (const float*)d_in[3];
    const float* wo = (const float*)d_in[4];
    float* out = (float*)d_out;
    (void)in_sizes; (void)n_in; (void)out_size;

    cudaFuncSetAttribute(qkv_tc, cudaFuncAttributeMaxDynamicSharedMemorySize,
                         G_SMEM_BYTES);
    cudaFuncSetAttribute(attn_tc, cudaFuncAttributeMaxDynamicSharedMemorySize,
                         ATTN_SMEM_BYTES);
    cudaFuncSetAttribute(proj_tc, cudaFuncAttributeMaxDynamicSharedMemorySize,
                         G_SMEM_BYTES);

    qkv_tc<<<dim3(NB * SEQ / 64, 3), 256, G_SMEM_BYTES>>>(x, wq, wk, wv);
    attn_tc<<<dim3(CPB, NB), 128, ATTN_SMEM_BYTES>>>();
    attn_combine<<<dim3(NQT, NB), 256>>>();
    proj_tc<<<dim3(NB * SEQ / 64, DM / 128), 256, G_SMEM_BYTES>>>(wo, out);
}

// round 8
// speedup vs baseline: 1.0394x; 1.0394x over previous
#include <cuda_runtime.h>
#include <math.h>

#define NB 4
#define SEQ 2048
#define DM 1024
#define DH 128
#define CHUNK 8                 // kv tiles (of 64) per attention CTA
#define NQT (SEQ / 64)          // 32 q-tiles
#define CPB 80                  // chunks per batch = 8*(1+2+3+4)
typedef unsigned int U32;

// Scratch (device globals: allocation-free rule)
__device__ float g_q[NB * SEQ * DH];
__device__ float g_k[NB * SEQ * DH];
__device__ float g_v[NB * SEQ * DH];
__device__ float g_ctx[NB * SEQ * DH];
// split-KV partials: [b][qt][kc][64 rows][128] + per-row m,l
__device__ float g_pO[NB * NQT * 4 * 64 * DH];
__device__ float g_pm[NB * NQT * 4 * 64];
__device__ float g_pl[NB * NQT * 4 * 64];

// ---------------------------------------------------------------------------
__device__ __forceinline__ U32 f2tf(float f) {
    U32 u;
    asm("cvt.rna.tf32.f32 %0, %1;" : "=r"(u) : "f"(f));
    return u;
}
__device__ __forceinline__ void mma8(float* c, const U32* a, const U32* b) {
    asm volatile(
        "mma.sync.aligned.m16n8k8.row.col.f32.tf32.tf32.f32 "
        "{%0,%1,%2,%3}, {%4,%5,%6,%7}, {%8,%9}, {%0,%1,%2,%3};\n"
        : "+f"(c[0]), "+f"(c[1]), "+f"(c[2]), "+f"(c[3])
        : "r"(a[0]), "r"(a[1]), "r"(a[2]), "r"(a[3]),
          "r"(b[0]), "r"(b[1]));
}

// ---------------------------------------------------------------------------
// Kernel 1: QKV projection, tf32 TC, BK=64, register-prefetch double buffer.
// grid=(128,3), 256 thr; CTA 64x128; warps 2x4 (warp tile 32x32).
// Smem (dynamic, tf32 words): Xs[64][68] + Ws[64][136] = 52224 B.
// 16 K-iterations; 64 MMAs/warp between barriers.
// ---------------------------------------------------------------------------
#define QKV_SMEM_WORDS (64 * 68 + 64 * 136)
#define QKV_SMEM_BYTES (QKV_SMEM_WORDS * 4)

__global__ __launch_bounds__(256) void qkv_tc(
    const float* __restrict__ x,
    const float* __restrict__ wq,
    const float* __restrict__ wk,
    const float* __restrict__ wv)
{
    extern __shared__ U32 smq[];
    U32* Xs = smq;               // stride 68  (68%32==4 -> A frags conflict-free)
    U32* Ws = smq + 64 * 68;     // stride 136 (8lc+lr -> B frags conflict-free)

    const int tid = threadIdx.x;
    const int lane = tid & 31;
    const int wid = tid >> 5;
    const int wm = wid >> 2;
    const int wn = wid & 3;
    const int m0 = blockIdx.x * 64;
    const int lr = lane >> 2;
    const int lc = lane & 3;

    const float* w;
    float* o;
    if (blockIdx.y == 0)      { w = wq; o = g_q; }
    else if (blockIdx.y == 1) { w = wk; o = g_k; }
    else                      { w = wv; o = g_v; }

    // staging: X 64x64 -> 4 float4/thr (16 thr/row), W 64x128 -> 8 float4/thr
    float4 xr[4], wr[8];
    #pragma unroll
    for (int i = 0; i < 4; i++) {
        int idx = tid + i * 256;
        int r = idx >> 4, c = (idx & 15) * 4;
        xr[i] = *(const float4*)(x + (size_t)(m0 + r) * DM + c);
    }
    #pragma unroll
    for (int i = 0; i < 8; i++) {
        int idx = tid + i * 256;
        int r = idx >> 5, c = (idx & 31) * 4;
        wr[i] = *(const float4*)(w + (size_t)r * DH + c);
    }

    float acc[2][4][4];
    #pragma unroll
    for (int mt = 0; mt < 2; mt++)
        #pragma unroll
        for (int nt = 0; nt < 4; nt++)
            #pragma unroll
            for (int j = 0; j < 4; j++) acc[mt][nt][j] = 0.f;

    for (int k0 = 0; k0 < DM; k0 += 64) {
        // commit staged tiles to smem (tf32 conversion here, once)
        #pragma unroll
        for (int i = 0; i < 4; i++) {
            int idx = tid + i * 256;
            int r = idx >> 4, c = (idx & 15) * 4;
            *(uint4*)&Xs[r * 68 + c] =
                make_uint4(f2tf(xr[i].x), f2tf(xr[i].y), f2tf(xr[i].z), f2tf(xr[i].w));
        }
        #pragma unroll
        for (int i = 0; i < 8; i++) {
            int idx = tid + i * 256;
            int r = idx >> 5, c = (idx & 31) * 4;
            *(uint4*)&Ws[r * 136 + c] =
                make_uint4(f2tf(wr[i].x), f2tf(wr[i].y), f2tf(wr[i].z), f2tf(wr[i].w));
        }
        __syncthreads();

        // prefetch next K-slice while 64 MMAs/warp run
        if (k0 + 64 < DM) {
            #pragma unroll
            for (int i = 0; i < 4; i++) {
                int idx = tid + i * 256;
                int r = idx >> 4, c = (idx & 15) * 4;
                xr[i] = *(const float4*)(x + (size_t)(m0 + r) * DM + k0 + 64 + c);
            }
            #pragma unroll
            for (int i = 0; i < 8; i++) {
                int idx = tid + i * 256;
                int r = idx >> 5, c = (idx & 31) * 4;
                wr[i] = *(const float4*)(w + (size_t)(k0 + 64 + r) * DH + c);
            }
        }

        #pragma unroll
        for (int q8 = 0; q8 < 8; q8++) {
            int kb = q8 * 8;
            U32 a[2][4], b[4][2];
            #pragma unroll
            for (int mt = 0; mt < 2; mt++) {
                int r = wm * 32 + mt * 16 + lr;
                a[mt][0] = Xs[r * 68 + kb + lc];
                a[mt][1] = Xs[(r + 8) * 68 + kb + lc];
                a[mt][2] = Xs[r * 68 + kb + lc + 4];
                a[mt][3] = Xs[(r + 8) * 68 + kb + lc + 4];
            }
            #pragma unroll
            for (int nt = 0; nt < 4; nt++) {
                int n = wn * 32 + nt * 8 + lr;
                b[nt][0] = Ws[(kb + lc) * 136 + n];
                b[nt][1] = Ws[(kb + lc + 4) * 136 + n];
            }
            #pragma unroll
            for (int mt = 0; mt < 2; mt++)
                #pragma unroll
                for (int nt = 0; nt < 4; nt++)
                    mma8(acc[mt][nt], a[mt], b[nt]);
        }
        __syncthreads();
    }

    #pragma unroll
    for (int mt = 0; mt < 2; mt++)
        #pragma unroll
        for (int nt = 0; nt < 4; nt++) {
            int r = m0 + wm * 32 + mt * 16 + lr;
            int cc = wn * 32 + nt * 8 + 2 * lc;
            *(float2*)(o + (size_t)r * DH + cc) =
                make_float2(acc[mt][nt][0], acc[mt][nt][1]);
            *(float2*)(o + (size_t)(r + 8) * DH + cc) =
                make_float2(acc[mt][nt][2], acc[mt][nt][3]);
        }
}

// ---------------------------------------------------------------------------
// Kernel 2: split-KV causal flash attention (tf32 TC). [R3 version, unchanged]
// grid=(80,4), 128 thr (4 warps; each warp owns 16 query rows).
// Smem: Qs[64*132] | KV union[64*136] | Ps[64*68] = 86016 B -> 2 CTAs/SM.
// ---------------------------------------------------------------------------
#define ATTN_SMEM_WORDS (64 * 132 + 64 * 136 + 64 * 68)
#define ATTN_SMEM_BYTES (ATTN_SMEM_WORDS * 4)

__global__ __launch_bounds__(128) void attn_tc()
{
    extern __shared__ U32 sm[];
    U32* Qs = sm;                    // stride 132
    U32* KV = sm + 64 * 132;         // union: K stride 132 / V stride 136
    U32* Ps = KV + 64 * 136;         // stride 68

    const int tid = threadIdx.x;
    const int lane = tid & 31;
    const int wid = tid >> 5;
    const int lr = lane >> 2;
    const int lc = lane & 3;
    const int b = blockIdx.y;
    const float scale = 0.088388347648318447f;   // 1/sqrt(128)

    // map blockIdx.x -> (q-tile, kv-chunk)
    int c = blockIdx.x, qt = 0, start = 0;
    for (;;) {
        int n = qt / 8 + 1;
        if (c < start + n) break;
        start += n;
        qt++;
    }
    const int kc = c - start;
    const int kt0 = kc * CHUNK;
    const int kt1 = min(kt0 + CHUNK, qt + 1);
    const int q0 = qt * 64;

    const float* qg = g_q + (size_t)b * SEQ * DH;
    const float* kg = g_k + (size_t)b * SEQ * DH;
    const float* vg = g_v + (size_t)b * SEQ * DH;

    // Q tile (pre-scaled tf32)
    #pragma unroll
    for (int i = 0; i < 16; i++) {
        int idx = tid + i * 128;
        int r = idx >> 5, c4 = idx & 31;
        float4 v = *(const float4*)(qg + (size_t)(q0 + r) * DH + c4 * 4);
        *(uint4*)&Qs[r * 132 + c4 * 4] = make_uint4(
            f2tf(v.x * scale), f2tf(v.y * scale),
            f2tf(v.z * scale), f2tf(v.w * scale));
    }

    float m0v = -1e30f, m1v = -1e30f, l0 = 0.f, l1 = 0.f;
    float O[16][4];
    #pragma unroll
    for (int nt = 0; nt < 16; nt++)
        #pragma unroll
        for (int j = 0; j < 4; j++) O[nt][j] = 0.f;

    const int rloc = wid * 16 + lr;

    for (int t = kt0; t < kt1; t++) {
        const int k0row = t * 64;
        __syncthreads();                          // prev PV reads of KV done (+Q ready)
        // K tile, stride 132
        #pragma unroll
        for (int i = 0; i < 16; i++) {
            int idx = tid + i * 128;
            int r = idx >> 5, c4 = idx & 31;
            float4 kv = *(const float4*)(kg + (size_t)(k0row + r) * DH + c4 * 4);
            *(uint4*)&KV[r * 132 + c4 * 4] =
                make_uint4(f2tf(kv.x), f2tf(kv.y), f2tf(kv.z), f2tf(kv.w));
        }
        __syncthreads();

        // S = Q @ K^T
        float sc[8][4];
        #pragma unroll
        for (int nt = 0; nt < 8; nt++)
            #pragma unroll
            for (int j = 0; j < 4; j++) sc[nt][j] = 0.f;

        #pragma unroll
        for (int k8 = 0; k8 < 16; k8++) {
            int kb = k8 * 8;
            U32 a[4];
            a[0] = Qs[rloc * 132 + kb + lc];
            a[1] = Qs[(rloc + 8) * 132 + kb + lc];
            a[2] = Qs[rloc * 132 + kb + lc + 4];
            a[3] = Qs[(rloc + 8) * 132 + kb + lc + 4];
            #pragma unroll
            for (int nt = 0; nt < 8; nt++) {
                U32 bb[2];
                int n = nt * 8 + lr;
                bb[0] = KV[n * 132 + kb + lc];
                bb[1] = KV[n * 132 + kb + lc + 4];
                mma8(sc[nt], a, bb);
            }
        }

        if (t == qt) {                             // diagonal tile: causal mask
            #pragma unroll
            for (int nt = 0; nt < 8; nt++) {
                int c0 = nt * 8 + 2 * lc;
                if (c0 > rloc)         sc[nt][0] = -1e30f;
                if (c0 + 1 > rloc)     sc[nt][1] = -1e30f;
                if (c0 > rloc + 8)     sc[nt][2] = -1e30f;
                if (c0 + 1 > rloc + 8) sc[nt][3] = -1e30f;
            }
        }

        // online softmax (rows rloc, rloc+8)
        float mx0 = -1e30f, mx1 = -1e30f;
        #pragma unroll
        for (int nt = 0; nt < 8; nt++) {
            mx0 = fmaxf(mx0, fmaxf(sc[nt][0], sc[nt][1]));
            mx1 = fmaxf(mx1, fmaxf(sc[nt][2], sc[nt][3]));
        }
        mx0 = fmaxf(mx0, __shfl_xor_sync(0xffffffffu, mx0, 1));
        mx0 = fmaxf(mx0, __shfl_xor_sync(0xffffffffu, mx0, 2));
        mx1 = fmaxf(mx1, __shfl_xor_sync(0xffffffffu, mx1, 1));
        mx1 = fmaxf(mx1, __shfl_xor_sync(0xffffffffu, mx1, 2));

        float mn0 = fmaxf(m0v, mx0), mn1 = fmaxf(m1v, mx1);
        float cr0 = __expf(m0v - mn0), cr1 = __expf(m1v - mn1);
        m0v = mn0; m1v = mn1;

        float s0 = 0.f, s1 = 0.f;
        #pragma unroll
        for (int nt = 0; nt < 8; nt++) {
            float p0 = __expf(sc[nt][0] - mn0);
            float p1 = __expf(sc[nt][1] - mn0);
            float p2 = __expf(sc[nt][2] - mn1);
            float p3 = __expf(sc[nt][3] - mn1);
            s0 += p0 + p1;
            s1 += p2 + p3;
            int cc = nt * 8 + 2 * lc;
            *(uint2*)&Ps[rloc * 68 + cc]       = make_uint2(f2tf(p0), f2tf(p1));
            *(uint2*)&Ps[(rloc + 8) * 68 + cc] = make_uint2(f2tf(p2), f2tf(p3));
        }
        s0 += __shfl_xor_sync(0xffffffffu, s0, 1);
        s0 += __shfl_xor_sync(0xffffffffu, s0, 2);
        s1 += __shfl_xor_sync(0xffffffffu, s1, 1);
        s1 += __shfl_xor_sync(0xffffffffu, s1, 2);
        l0 = l0 * cr0 + s0;
        l1 = l1 * cr1 + s1;

        #pragma unroll
        for (int nt = 0; nt < 16; nt++) {
            O[nt][0] *= cr0; O[nt][1] *= cr0;
            O[nt][2] *= cr1; O[nt][3] *= cr1;
        }

        __syncthreads();                          // K reads + Ps writes complete
        // V tile, stride 136 (same buffer)
        #pragma unroll
        for (int i = 0; i < 16; i++) {
            int idx = tid + i * 128;
            int r = idx >> 5, c4 = idx & 31;
            float4 vv = *(const float4*)(vg + (size_t)(k0row + r) * DH + c4 * 4);
            *(uint4*)&KV[r * 136 + c4 * 4] =
                make_uint4(f2tf(vv.x), f2tf(vv.y), f2tf(vv.z), f2tf(vv.w));
        }
        __syncthreads();

        // O += P @ V
        #pragma unroll
        for (int k8 = 0; k8 < 8; k8++) {
            int kb = k8 * 8;
            U32 a[4];
            a[0] = Ps[rloc * 68 + kb + lc];
            a[1] = Ps[(rloc + 8) * 68 + kb + lc];
            a[2] = Ps[rloc * 68 + kb + lc + 4];
            a[3] = Ps[(rloc + 8) * 68 + kb + lc + 4];
            #pragma unroll
            for (int nt = 0; nt < 16; nt++) {
                U32 bb[2];
                int n = nt * 8 + lr;
                bb[0] = KV[(kb + lc) * 136 + n];
                bb[1] = KV[(kb + lc + 4) * 136 + n];
                mma8(O[nt], a, bb);
            }
        }
    }

    // write partials (unnormalized O, plus m, l)
    const size_t pbase = (size_t)((b * NQT + qt) * 4 + kc);
    float* pO = g_pO + pbase * 64 * DH;
    #pragma unroll
    for (int nt = 0; nt < 16; nt++) {
        int cc = nt * 8 + 2 * lc;
        *(float2*)&pO[rloc * DH + cc]       = make_float2(O[nt][0], O[nt][1]);
        *(float2*)&pO[(rloc + 8) * DH + cc] = make_float2(O[nt][2], O[nt][3]);
    }
    if (lc == 0) {
        g_pm[pbase * 64 + rloc]     = m0v;
        g_pl[pbase * 64 + rloc]     = l0;
        g_pm[pbase * 64 + rloc + 8] = m1v;
        g_pl[pbase * 64 + rloc + 8] = l1;
    }
}

// ---------------------------------------------------------------------------
// Kernel 2b: combine split-KV partials -> g_ctx. grid=(32,4), 256 thr.
// ---------------------------------------------------------------------------
__global__ __launch_bounds__(256) void attn_combine()
{
    const int qt = blockIdx.x, b = blockIdx.y;
    const int nc = qt / 8 + 1;
    const int row = threadIdx.x >> 2;
    const int cs = (threadIdx.x & 3) * 32;
    const size_t pb = (size_t)(b * NQT + qt) * 4;

    float m[4], l[4], w[4];
    float M = -1e30f;
    #pragma unroll 4
    for (int i = 0; i < nc; i++) {
        m[i] = g_pm[(pb + i) * 64 + row];
        l[i] = g_pl[(pb + i) * 64 + row];
        M = fmaxf(M, m[i]);
    }
    float L = 0.f;
    #pragma unroll 4
    for (int i = 0; i < nc; i++) {
        w[i] = __expf(m[i] - M);
        L += w[i] * l[i];
    }
    const float inv = 1.f / L;

    float acc[32];
    #pragma unroll
    for (int j = 0; j < 32; j++) acc[j] = 0.f;

    #pragma unroll 4
    for (int i = 0; i < nc; i++) {
        const float* p = g_pO + (pb + i) * 64 * DH + (size_t)row * DH + cs;
        float wi = w[i];
        #pragma unroll
        for (int j = 0; j < 8; j++) {
            float4 v = *(const float4*)(p + j * 4);
            acc[j * 4 + 0] += wi * v.x;
            acc[j * 4 + 1] += wi * v.y;
            acc[j * 4 + 2] += wi * v.z;
            acc[j * 4 + 3] += wi * v.w;
        }
    }

    float* cg = g_ctx + ((size_t)b * SEQ + qt * 64 + row) * DH + cs;
    #pragma unroll
    for (int j = 0; j < 8; j++)
        *(float4*)(cg + j * 4) = make_float4(acc[j * 4] * inv, acc[j * 4 + 1] * inv,
                                             acc[j * 4 + 2] * inv, acc[j * 4 + 3] * inv);
}

// ---------------------------------------------------------------------------
// Kernel 3: output projection, BK=64 (2 iters), register prefetch.
// grid=(128,8), 256 thr; CTA 64x128.
// ---------------------------------------------------------------------------
__global__ __launch_bounds__(256) void proj_tc(
    const float* __restrict__ wo, float* __restrict__ out)
{
    extern __shared__ U32 smq[];
    U32* Xs = smq;               // stride 68
    U32* Ws = smq + 64 * 68;     // stride 136

    const int tid = threadIdx.x;
    const int lane = tid & 31;
    const int wid = tid >> 5;
    const int wm = wid >> 2;
    const int wn = wid & 3;
    const int m0 = blockIdx.x * 64;
    const int n0 = blockIdx.y * 128;
    const int lr = lane >> 2;
    const int lc = lane & 3;

    float4 xr[4], wr[8];
    #pragma unroll
    for (int i = 0; i < 4; i++) {
        int idx = tid + i * 256;
        int r = idx >> 4, c = (idx & 15) * 4;
        xr[i] = *(const float4*)(g_ctx + (size_t)(m0 + r) * DH + c);
    }
    #pragma unroll
    for (int i = 0; i < 8; i++) {
        int idx = tid + i * 256;
        int r = idx >> 5, c = (idx & 31) * 4;
        wr[i] = *(const float4*)(wo + (size_t)r * DM + n0 + c);
    }

    float acc[2][4][4];
    #pragma unroll
    for (int mt = 0; mt < 2; mt++)
        #pragma unroll
        for (int nt = 0; nt < 4; nt++)
            #pragma unroll
            for (int j = 0; j < 4; j++) acc[mt][nt][j] = 0.f;

    for (int k0 = 0; k0 < DH; k0 += 64) {
        #pragma unroll
        for (int i = 0; i < 4; i++) {
            int idx = tid + i * 256;
            int r = idx >> 4, c = (idx & 15) * 4;
            *(uint4*)&Xs[r * 68 + c] =
                make_uint4(f2tf(xr[i].x), f2tf(xr[i].y), f2tf(xr[i].z), f2tf(xr[i].w));
        }
        #pragma unroll
        for (int i = 0; i < 8; i++) {
            int idx = tid + i * 256;
            int r = idx >> 5, c = (idx & 31) * 4;
            *(uint4*)&Ws[r * 136 + c] =
                make_uint4(f2tf(wr[i].x), f2tf(wr[i].y), f2tf(wr[i].z), f2tf(wr[i].w));
        }
        __syncthreads();

        if (k0 + 64 < DH) {
            #pragma unroll
            for (int i = 0; i < 4; i++) {
                int idx = tid + i * 256;
                int r = idx >> 4, c = (idx & 15) * 4;
                xr[i] = *(const float4*)(g_ctx + (size_t)(m0 + r) * DH + k0 + 64 + c);
            }
            #pragma unroll
            for (int i = 0; i < 8; i++) {
                int idx = tid + i * 256;
                int r = idx >> 5, c = (idx & 31) * 4;
                wr[i] = *(const float4*)(wo + (size_t)(k0 + 64 + r) * DM + n0 + c);
            }
        }

        #pragma unroll
        for (int q8 = 0; q8 < 8; q8++) {
            int kb = q8 * 8;
            U32 a[2][4], b[4][2];
            #pragma unroll
            for (int mt = 0; mt < 2; mt++) {
                int r = wm * 32 + mt * 16 + lr;
                a[mt][0] = Xs[r * 68 + kb + lc];
                a[mt][1] = Xs[(r + 8) * 68 + kb + lc];
                a[mt][2] = Xs[r * 68 + kb + lc + 4];
                a[mt][3] = Xs[(r + 8) * 68 + kb + lc + 4];
            }
            #pragma unroll
            for (int nt = 0; nt < 4; nt++) {
                int n = wn * 32 + nt * 8 + lr;
                b[nt][0] = Ws[(kb + lc) * 136 + n];
                b[nt][1] = Ws[(kb + lc + 4) * 136 + n];
            }
            #pragma unroll
            for (int mt = 0; mt < 2; mt++)
                #pragma unroll
                for (int nt = 0; nt < 4; nt++)
                    mma8(acc[mt][nt], a[mt], b[nt]);
        }
        __syncthreads();
    }

    #pragma unroll
    for (int mt = 0; mt < 2; mt++)
        #pragma unroll
        for (int nt = 0; nt < 4; nt++) {
            int r = m0 + wm * 32 + mt * 16 + lr;
            int cc = n0 + wn * 32 + nt * 8 + 2 * lc;
            *(float2*)(out + (size_t)r * DM + cc) =
                make_float2(acc[mt][nt][0], acc[mt][nt][1]);
            *(float2*)(out + (size_t)(r + 8) * DM + cc) =
                make_float2(acc[mt][nt][2], acc[mt][nt][3]);
        }
}

// ---------------------------------------------------------------------------
extern "C" void kernel_launch(void* const* d_in, const int* in_sizes, int n_in,
                              void* d_out, int out_size)
{
    const float* x  = (const float*)d_in[0];
    const float* wq = (const float*)d_in[1];
    const float* wk = (const float*)d_in[2];
    const float* wv = (const float*)d_in[3];
    const float* wo = (const float*)d_in[4];
    float* out = (float*)d_out;
    (void)in_sizes; (void)n_in; (void)out_size;

    cudaFuncSetAttribute(qkv_tc, cudaFuncAttributeMaxDynamicSharedMemorySize,
                         QKV_SMEM_BYTES);
    cudaFuncSetAttribute(attn_tc, cudaFuncAttributeMaxDynamicSharedMemorySize,
                         ATTN_SMEM_BYTES);
    cudaFuncSetAttribute(proj_tc, cudaFuncAttributeMaxDynamicSharedMemorySize,
                         QKV_SMEM_BYTES);

    qkv_tc<<<dim3(NB * SEQ / 64, 3), 256, QKV_SMEM_BYTES>>>(x, wq, wk, wv);
    attn_tc<<<dim3(CPB, NB), 128, ATTN_SMEM_BYTES>>>();
    attn_combine<<<dim3(NQT, NB), 256>>>();
    proj_tc<<<dim3(NB * SEQ / 64, DM / 128), 256, QKV_SMEM_BYTES>>>(wo, out);
}

// round 9
// speedup vs baseline: 1.0721x; 1.0315x over previous
#include <cuda_runtime.h>
#include <math.h>

#define NB 4
#define SEQ 2048
#define DM 1024
#define DH 128
#define CHUNK 8                 // kv tiles (of 64) per attention CTA
#define NQT (SEQ / 64)          // 32 q-tiles
#define CPB 80                  // chunks per batch = 8*(1+2+3+4)
typedef unsigned int U32;

// Scratch (device globals: allocation-free rule)
__device__ float g_q[NB * SEQ * DH];
__device__ float g_k[NB * SEQ * DH];
__device__ float g_v[NB * SEQ * DH];
__device__ float g_ctx[NB * SEQ * DH];
// split-KV partials: [b][qt][kc][64 rows][128] + per-row m,l
__device__ float g_pO[NB * NQT * 4 * 64 * DH];
__device__ float g_pm[NB * NQT * 4 * 64];
__device__ float g_pl[NB * NQT * 4 * 64];

// ---------------------------------------------------------------------------
__device__ __forceinline__ U32 f2tf(float f) {
    U32 u;
    asm("cvt.rna.tf32.f32 %0, %1;" : "=r"(u) : "f"(f));
    return u;
}
__device__ __forceinline__ void mma8(float* c, const U32* a, const U32* b) {
    asm volatile(
        "mma.sync.aligned.m16n8k8.row.col.f32.tf32.tf32.f32 "
        "{%0,%1,%2,%3}, {%4,%5,%6,%7}, {%8,%9}, {%0,%1,%2,%3};\n"
        : "+f"(c[0]), "+f"(c[1]), "+f"(c[2]), "+f"(c[3])
        : "r"(a[0]), "r"(a[1]), "r"(a[2]), "r"(a[3]),
          "r"(b[0]), "r"(b[1]));
}

// ---------------------------------------------------------------------------
// Kernel 1: QKV projection, tf32 TC, BK=32, register-prefetch double buffer.
// grid=(128,3), 256 thr; CTA 64x128; warps 2x4 (warp tile 32x32).  [R4 exact]
// ---------------------------------------------------------------------------
__global__ __launch_bounds__(256) void qkv_tc(
    const float* __restrict__ x,
    const float* __restrict__ wq,
    const float* __restrict__ wk,
    const float* __restrict__ wv)
{
    __shared__ U32 Xs[64 * 36];
    __shared__ U32 Ws[32 * 136];

    const int tid = threadIdx.x;
    const int lane = tid & 31;
    const int wid = tid >> 5;
    const int wm = wid >> 2;
    const int wn = wid & 3;
    const int m0 = blockIdx.x * 64;
    const int lr = lane >> 2;
    const int lc = lane & 3;

    const float* w;
    float* o;
    if (blockIdx.y == 0)      { w = wq; o = g_q; }
    else if (blockIdx.y == 1) { w = wk; o = g_k; }
    else                      { w = wv; o = g_v; }

    const int xr_r = tid >> 3, xr_c = (tid & 7) * 4;   // X 64x32: 2 f4/thr
    const int wr_k = tid >> 5, wr_c = (tid & 31) * 4;  // W 32x128: 4 f4/thr
    float4 xr[2], wr[4];

    #pragma unroll
    for (int i = 0; i < 2; i++)
        xr[i] = *(const float4*)(x + (size_t)(m0 + xr_r + i * 32) * DM + xr_c);
    #pragma unroll
    for (int i = 0; i < 4; i++)
        wr[i] = *(const float4*)(w + (size_t)(wr_k + i * 8) * DH + wr_c);

    float acc[2][4][4];
    #pragma unroll
    for (int mt = 0; mt < 2; mt++)
        #pragma unroll
        for (int nt = 0; nt < 4; nt++)
            #pragma unroll
            for (int j = 0; j < 4; j++) acc[mt][nt][j] = 0.f;

    for (int k0 = 0; k0 < DM; k0 += 32) {
        #pragma unroll
        for (int i = 0; i < 2; i++)
            *(uint4*)&Xs[(xr_r + i * 32) * 36 + xr_c] =
                make_uint4(f2tf(xr[i].x), f2tf(xr[i].y), f2tf(xr[i].z), f2tf(xr[i].w));
        #pragma unroll
        for (int i = 0; i < 4; i++)
            *(uint4*)&Ws[(wr_k + i * 8) * 136 + wr_c] =
                make_uint4(f2tf(wr[i].x), f2tf(wr[i].y), f2tf(wr[i].z), f2tf(wr[i].w));
        __syncthreads();

        if (k0 + 32 < DM) {
            #pragma unroll
            for (int i = 0; i < 2; i++)
                xr[i] = *(const float4*)(x + (size_t)(m0 + xr_r + i * 32) * DM + k0 + 32 + xr_c);
            #pragma unroll
            for (int i = 0; i < 4; i++)
                wr[i] = *(const float4*)(w + (size_t)(k0 + 32 + wr_k + i * 8) * DH + wr_c);
        }

        #pragma unroll
        for (int q8 = 0; q8 < 4; q8++) {
            int kb = q8 * 8;
            U32 a[2][4], b[4][2];
            #pragma unroll
            for (int mt = 0; mt < 2; mt++) {
                int r = wm * 32 + mt * 16 + lr;
                a[mt][0] = Xs[r * 36 + kb + lc];
                a[mt][1] = Xs[(r + 8) * 36 + kb + lc];
                a[mt][2] = Xs[r * 36 + kb + lc + 4];
                a[mt][3] = Xs[(r + 8) * 36 + kb + lc + 4];
            }
            #pragma unroll
            for (int nt = 0; nt < 4; nt++) {
                int n = wn * 32 + nt * 8 + lr;
                b[nt][0] = Ws[(kb + lc) * 136 + n];
                b[nt][1] = Ws[(kb + lc + 4) * 136 + n];
            }
            #pragma unroll
            for (int mt = 0; mt < 2; mt++)
                #pragma unroll
                for (int nt = 0; nt < 4; nt++)
                    mma8(acc[mt][nt], a[mt], b[nt]);
        }
        __syncthreads();
    }

    #pragma unroll
    for (int mt = 0; mt < 2; mt++)
        #pragma unroll
        for (int nt = 0; nt < 4; nt++) {
            int r = m0 + wm * 32 + mt * 16 + lr;
            int cc = wn * 32 + nt * 8 + 2 * lc;
            *(float2*)(o + (size_t)r * DH + cc) =
                make_float2(acc[mt][nt][0], acc[mt][nt][1]);
            *(float2*)(o + (size_t)(r + 8) * DH + cc) =
                make_float2(acc[mt][nt][2], acc[mt][nt][3]);
        }
}

// ---------------------------------------------------------------------------
// Kernel 2: split-KV causal flash attention (tf32 TC). [R4 + LPT ordering]
// grid=(80,4), 128 thr. Chunks decoded from REVERSED blockIdx so the largest
// (8-tile) chunks launch first -> longest-processing-time schedule.
// Smem: Qs[64*132] | KV union[64*136] | Ps[64*68] = 86016 B -> 2 CTAs/SM.
// ---------------------------------------------------------------------------
#define ATTN_SMEM_WORDS (64 * 132 + 64 * 136 + 64 * 68)
#define ATTN_SMEM_BYTES (ATTN_SMEM_WORDS * 4)

__global__ __launch_bounds__(128) void attn_tc()
{
    extern __shared__ U32 sm[];
    U32* Qs = sm;                    // stride 132
    U32* KV = sm + 64 * 132;         // union: K stride 132 / V stride 136
    U32* Ps = KV + 64 * 136;         // stride 68

    const int tid = threadIdx.x;
    const int lane = tid & 31;
    const int wid = tid >> 5;
    const int lr = lane >> 2;
    const int lc = lane & 3;
    const int b = blockIdx.y;
    const float scale = 0.088388347648318447f;   // 1/sqrt(128)

    // LPT scheduling: reverse blockIdx so high-qt (8-tile) chunks start first.
    int c = CPB - 1 - blockIdx.x;
    int qt = 0, start = 0;
    for (;;) {
        int n = qt / 8 + 1;
        if (c < start + n) break;
        start += n;
        qt++;
    }
    const int kc = c - start;
    const int kt0 = kc * CHUNK;
    const int kt1 = min(kt0 + CHUNK, qt + 1);
    const int q0 = qt * 64;

    const float* qg = g_q + (size_t)b * SEQ * DH;
    const float* kg = g_k + (size_t)b * SEQ * DH;
    const float* vg = g_v + (size_t)b * SEQ * DH;

    // Q tile (pre-scaled tf32)
    #pragma unroll
    for (int i = 0; i < 16; i++) {
        int idx = tid + i * 128;
        int r = idx >> 5, c4 = idx & 31;
        float4 v = *(const float4*)(qg + (size_t)(q0 + r) * DH + c4 * 4);
        *(uint4*)&Qs[r * 132 + c4 * 4] = make_uint4(
            f2tf(v.x * scale), f2tf(v.y * scale),
            f2tf(v.z * scale), f2tf(v.w * scale));
    }

    float m0v = -1e30f, m1v = -1e30f, l0 = 0.f, l1 = 0.f;
    float O[16][4];
    #pragma unroll
    for (int nt = 0; nt < 16; nt++)
        #pragma unroll
        for (int j = 0; j < 4; j++) O[nt][j] = 0.f;

    const int rloc = wid * 16 + lr;

    for (int t = kt0; t < kt1; t++) {
        const int k0row = t * 64;
        __syncthreads();                          // prev PV reads of KV done (+Q ready)
        #pragma unroll
        for (int i = 0; i < 16; i++) {
            int idx = tid + i * 128;
            int r = idx >> 5, c4 = idx & 31;
            float4 kv = *(const float4*)(kg + (size_t)(k0row + r) * DH + c4 * 4);
            *(uint4*)&KV[r * 132 + c4 * 4] =
                make_uint4(f2tf(kv.x), f2tf(kv.y), f2tf(kv.z), f2tf(kv.w));
        }
        __syncthreads();

        // S = Q @ K^T
        float sc[8][4];
        #pragma unroll
        for (int nt = 0; nt < 8; nt++)
            #pragma unroll
            for (int j = 0; j < 4; j++) sc[nt][j] = 0.f;

        #pragma unroll
        for (int k8 = 0; k8 < 16; k8++) {
            int kb = k8 * 8;
            U32 a[4];
            a[0] = Qs[rloc * 132 + kb + lc];
            a[1] = Qs[(rloc + 8) * 132 + kb + lc];
            a[2] = Qs[rloc * 132 + kb + lc + 4];
            a[3] = Qs[(rloc + 8) * 132 + kb + lc + 4];
            #pragma unroll
            for (int nt = 0; nt < 8; nt++) {
                U32 bb[2];
                int n = nt * 8 + lr;
                bb[0] = KV[n * 132 + kb + lc];
                bb[1] = KV[n * 132 + kb + lc + 4];
                mma8(sc[nt], a, bb);
            }
        }

        if (t == qt) {                             // diagonal tile: causal mask
            #pragma unroll
            for (int nt = 0; nt < 8; nt++) {
                int c0 = nt * 8 + 2 * lc;
                if (c0 > rloc)         sc[nt][0] = -1e30f;
                if (c0 + 1 > rloc)     sc[nt][1] = -1e30f;
                if (c0 > rloc + 8)     sc[nt][2] = -1e30f;
                if (c0 + 1 > rloc + 8) sc[nt][3] = -1e30f;
            }
        }

        // online softmax (rows rloc, rloc+8)
        float mx0 = -1e30f, mx1 = -1e30f;
        #pragma unroll
        for (int nt = 0; nt < 8; nt++) {
            mx0 = fmaxf(mx0, fmaxf(sc[nt][0], sc[nt][1]));
            mx1 = fmaxf(mx1, fmaxf(sc[nt][2], sc[nt][3]));
        }
        mx0 = fmaxf(mx0, __shfl_xor_sync(0xffffffffu, mx0, 1));
        mx0 = fmaxf(mx0, __shfl_xor_sync(0xffffffffu, mx0, 2));
        mx1 = fmaxf(mx1, __shfl_xor_sync(0xffffffffu, mx1, 1));
        mx1 = fmaxf(mx1, __shfl_xor_sync(0xffffffffu, mx1, 2));

        float mn0 = fmaxf(m0v, mx0), mn1 = fmaxf(m1v, mx1);
        float cr0 = __expf(m0v - mn0), cr1 = __expf(m1v - mn1);
        m0v = mn0; m1v = mn1;

        float s0 = 0.f, s1 = 0.f;
        #pragma unroll
        for (int nt = 0; nt < 8; nt++) {
            float p0 = __expf(sc[nt][0] - mn0);
            float p1 = __expf(sc[nt][1] - mn0);
            float p2 = __expf(sc[nt][2] - mn1);
            float p3 = __expf(sc[nt][3] - mn1);
            s0 += p0 + p1;
            s1 += p2 + p3;
            int cc = nt * 8 + 2 * lc;
            *(uint2*)&Ps[rloc * 68 + cc]       = make_uint2(f2tf(p0), f2tf(p1));
            *(uint2*)&Ps[(rloc + 8) * 68 + cc] = make_uint2(f2tf(p2), f2tf(p3));
        }
        s0 += __shfl_xor_sync(0xffffffffu, s0, 1);
        s0 += __shfl_xor_sync(0xffffffffu, s0, 2);
        s1 += __shfl_xor_sync(0xffffffffu, s1, 1);
        s1 += __shfl_xor_sync(0xffffffffu, s1, 2);
        l0 = l0 * cr0 + s0;
        l1 = l1 * cr1 + s1;

        #pragma unroll
        for (int nt = 0; nt < 16; nt++) {
            O[nt][0] *= cr0; O[nt][1] *= cr0;
            O[nt][2] *= cr1; O[nt][3] *= cr1;
        }

        __syncthreads();                          // K reads + Ps writes complete
        #pragma unroll
        for (int i = 0; i < 16; i++) {
            int idx = tid + i * 128;
            int r = idx >> 5, c4 = idx & 31;
            float4 vv = *(const float4*)(vg + (size_t)(k0row + r) * DH + c4 * 4);
            *(uint4*)&KV[r * 136 + c4 * 4] =
                make_uint4(f2tf(vv.x), f2tf(vv.y), f2tf(vv.z), f2tf(vv.w));
        }
        __syncthreads();

        // O += P @ V
        #pragma unroll
        for (int k8 = 0; k8 < 8; k8++) {
            int kb = k8 * 8;
            U32 a[4];
            a[0] = Ps[rloc * 68 + kb + lc];
            a[1] = Ps[(rloc + 8) * 68 + kb + lc];
            a[2] = Ps[rloc * 68 + kb + lc + 4];
            a[3] = Ps[(rloc + 8) * 68 + kb + lc + 4];
            #pragma unroll
            for (int nt = 0; nt < 16; nt++) {
                U32 bb[2];
                int n = nt * 8 + lr;
                bb[0] = KV[(kb + lc) * 136 + n];
                bb[1] = KV[(kb + lc + 4) * 136 + n];
                mma8(O[nt], a, bb);
            }
        }
    }

    // write partials (unnormalized O, plus m, l)
    const size_t pbase = (size_t)((b * NQT + qt) * 4 + kc);
    float* pO = g_pO + pbase * 64 * DH;
    #pragma unroll
    for (int nt = 0; nt < 16; nt++) {
        int cc = nt * 8 + 2 * lc;
        *(float2*)&pO[rloc * DH + cc]       = make_float2(O[nt][0], O[nt][1]);
        *(float2*)&pO[(rloc + 8) * DH + cc] = make_float2(O[nt][2], O[nt][3]);
    }
    if (lc == 0) {
        g_pm[pbase * 64 + rloc]     = m0v;
        g_pl[pbase * 64 + rloc]     = l0;
        g_pm[pbase * 64 + rloc + 8] = m1v;
        g_pl[pbase * 64 + rloc + 8] = l1;
    }
}

// ---------------------------------------------------------------------------
// Kernel 2b: combine split-KV partials -> g_ctx. grid=(32,4), 256 thr.
// ---------------------------------------------------------------------------
__global__ __launch_bounds__(256) void attn_combine()
{
    const int qt = blockIdx.x, b = blockIdx.y;
    const int nc = qt / 8 + 1;
    const int row = threadIdx.x >> 2;
    const int cs = (threadIdx.x & 3) * 32;
    const size_t pb = (size_t)(b * NQT + qt) * 4;

    float m[4], l[4], w[4];
    float M = -1e30f;
    #pragma unroll 4
    for (int i = 0; i < nc; i++) {
        m[i] = g_pm[(pb + i) * 64 + row];
        l[i] = g_pl[(pb + i) * 64 + row];
        M = fmaxf(M, m[i]);
    }
    float L = 0.f;
    #pragma unroll 4
    for (int i = 0; i < nc; i++) {
        w[i] = __expf(m[i] - M);
        L += w[i] * l[i];
    }
    const float inv = 1.f / L;

    float acc[32];
    #pragma unroll
    for (int j = 0; j < 32; j++) acc[j] = 0.f;

    #pragma unroll 4
    for (int i = 0; i < nc; i++) {
        const float* p = g_pO + (pb + i) * 64 * DH + (size_t)row * DH + cs;
        float wi = w[i];
        #pragma unroll
        for (int j = 0; j < 8; j++) {
            float4 v = *(const float4*)(p + j * 4);
            acc[j * 4 + 0] += wi * v.x;
            acc[j * 4 + 1] += wi * v.y;
            acc[j * 4 + 2] += wi * v.z;
            acc[j * 4 + 3] += wi * v.w;
        }
    }

    float* cg = g_ctx + ((size_t)b * SEQ + qt * 64 + row) * DH + cs;
    #pragma unroll
    for (int j = 0; j < 8; j++)
        *(float4*)(cg + j * 4) = make_float4(acc[j * 4] * inv, acc[j * 4 + 1] * inv,
                                             acc[j * 4 + 2] * inv, acc[j * 4 + 3] * inv);
}

// ---------------------------------------------------------------------------
// Kernel 3: output projection, BK=32, register prefetch. [R4 exact]
// grid=(128,8), 256 thr; CTA 64x128, K=128.
// ---------------------------------------------------------------------------
__global__ __launch_bounds__(256) void proj_tc(
    const float* __restrict__ wo, float* __restrict__ out)
{
    __shared__ U32 Xs[64 * 36];
    __shared__ U32 Ws[32 * 136];

    const int tid = threadIdx.x;
    const int lane = tid & 31;
    const int wid = tid >> 5;
    const int wm = wid >> 2;
    const int wn = wid & 3;
    const int m0 = blockIdx.x * 64;
    const int n0 = blockIdx.y * 128;
    const int lr = lane >> 2;
    const int lc = lane & 3;

    const int xr_r = tid >> 3, xr_c = (tid & 7) * 4;
    const int wr_k = tid >> 5, wr_c = (tid & 31) * 4;
    float4 xr[2], wr[4];

    #pragma unroll
    for (int i = 0; i < 2; i++)
        xr[i] = *(const float4*)(g_ctx + (size_t)(m0 + xr_r + i * 32) * DH + xr_c);
    #pragma unroll
    for (int i = 0; i < 4; i++)
        wr[i] = *(const float4*)(wo + (size_t)(wr_k + i * 8) * DM + n0 + wr_c);

    float acc[2][4][4];
    #pragma unroll
    for (int mt = 0; mt < 2; mt++)
        #pragma unroll
        for (int nt = 0; nt < 4; nt++)
            #pragma unroll
            for (int j = 0; j < 4; j++) acc[mt][nt][j] = 0.f;

    for (int k0 = 0; k0 < DH; k0 += 32) {
        #pragma unroll
        for (int i = 0; i < 2; i++)
            *(uint4*)&Xs[(xr_r + i * 32) * 36 + xr_c] =
                make_uint4(f2tf(xr[i].x), f2tf(xr[i].y), f2tf(xr[i].z), f2tf(xr[i].w));
        #pragma unroll
        for (int i = 0; i < 4; i++)
            *(uint4*)&Ws[(wr_k + i * 8) * 136 + wr_c] =
                make_uint4(f2tf(wr[i].x), f2tf(wr[i].y), f2tf(wr[i].z), f2tf(wr[i].w));
        __syncthreads();

        if (k0 + 32 < DH) {
            #pragma unroll
            for (int i = 0; i < 2; i++)
                xr[i] = *(const float4*)(g_ctx + (size_t)(m0 + xr_r + i * 32) * DH + k0 + 32 + xr_c);
            #pragma unroll
            for (int i = 0; i < 4; i++)
                wr[i] = *(const float4*)(wo + (size_t)(k0 + 32 + wr_k + i * 8) * DM + n0 + wr_c);
        }

        #pragma unroll
        for (int q8 = 0; q8 < 4; q8++) {
            int kb = q8 * 8;
            U32 a[2][4], b[4][2];
            #pragma unroll
            for (int mt = 0; mt < 2; mt++) {
                int r = wm * 32 + mt * 16 + lr;
                a[mt][0] = Xs[r * 36 + kb + lc];
                a[mt][1] = Xs[(r + 8) * 36 + kb + lc];
                a[mt][2] = Xs[r * 36 + kb + lc + 4];
                a[mt][3] = Xs[(r + 8) * 36 + kb + lc + 4];
            }
            #pragma unroll
            for (int nt = 0; nt < 4; nt++) {
                int n = wn * 32 + nt * 8 + lr;
                b[nt][0] = Ws[(kb + lc) * 136 + n];
                b[nt][1] = Ws[(kb + lc + 4) * 136 + n];
            }
            #pragma unroll
            for (int mt = 0; mt < 2; mt++)
                #pragma unroll
                for (int nt = 0; nt < 4; nt++)
                    mma8(acc[mt][nt], a[mt], b[nt]);
        }
        __syncthreads();
    }

    #pragma unroll
    for (int mt = 0; mt < 2; mt++)
        #pragma unroll
        for (int nt = 0; nt < 4; nt++) {
            int r = m0 + wm * 32 + mt * 16 + lr;
            int cc = n0 + wn * 32 + nt * 8 + 2 * lc;
            *(float2*)(out + (size_t)r * DM + cc) =
                make_float2(acc[mt][nt][0], acc[mt][nt][1]);
            *(float2*)(out + (size_t)(r + 8) * DM + cc) =
                make_float2(acc[mt][nt][2], acc[mt][nt][3]);
        }
}

// ---------------------------------------------------------------------------
extern "C" void kernel_launch(void* const* d_in, const int* in_sizes, int n_in,
                              void* d_out, int out_size)
{
    const float* x  = (const float*)d_in[0];
    const float* wq = (const float*)d_in[1];
    const float* wk = (const float*)d_in[2];
    const float* wv = (const float*)d_in[3];
    const float* wo = (const float*)d_in[4];
    float* out = (float*)d_out;
    (void)in_sizes; (void)n_in; (void)out_size;

    qkv_tc<<<dim3(NB * SEQ / 64, 3), 256>>>(x, wq, wk, wv);

    cudaFuncSetAttribute(attn_tc,
                         cudaFuncAttributeMaxDynamicSharedMemorySize,
                         ATTN_SMEM_BYTES);
    attn_tc<<<dim3(CPB, NB), 128, ATTN_SMEM_BYTES>>>();

    attn_combine<<<dim3(NQT, NB), 256>>>();

    proj_tc<<<dim3(NB * SEQ / 64, DM / 128), 256>>>(wo, out);
}

// round 12
// speedup vs baseline: 1.3351x; 1.2453x over previous
#include <cuda_runtime.h>
#include <math.h>

#define NB 4
#define SEQ 2048
#define DM 1024
#define DH 128
#define CHUNK 8                 // kv tiles (of 64) per attention CTA
#define NQT (SEQ / 64)          // 32 q-tiles
#define CPB 80                  // chunks per batch = 8*(1+2+3+4)
typedef unsigned int U32;

// Scratch (device globals: allocation-free rule)
__device__ float g_q[NB * SEQ * DH];
__device__ float g_k[NB * SEQ * DH];
__device__ float g_v[NB * SEQ * DH];
__device__ float g_ctx[NB * SEQ * DH];
// split-KV partials: [b][qt][kc][64 rows][128] + per-row m,l
__device__ float g_pO[NB * NQT * 4 * 64 * DH];
__device__ float g_pm[NB * NQT * 4 * 64];
__device__ float g_pl[NB * NQT * 4 * 64];

// ---------------------------------------------------------------------------
// fp16 helpers
// ---------------------------------------------------------------------------
// pack two fp32 -> half2 word: lo in low half, hi in high half
__device__ __forceinline__ U32 f2h2(float lo, float hi) {
    U32 u;
    asm("cvt.rn.f16x2.f32 %0, %1, %2;" : "=r"(u) : "f"(hi), "f"(lo));
    return u;
}
// D += A(16x16) * B(16x8); fp16 inputs, fp32 accumulate
__device__ __forceinline__ void mma16(float* c, const U32* a, const U32* b) {
    asm volatile(
        "mma.sync.aligned.m16n8k16.row.col.f32.f16.f16.f32 "
        "{%0,%1,%2,%3}, {%4,%5,%6,%7}, {%8,%9}, {%0,%1,%2,%3};\n"
        : "+f"(c[0]), "+f"(c[1]), "+f"(c[2]), "+f"(c[3])
        : "r"(a[0]), "r"(a[1]), "r"(a[2]), "r"(a[3]),
          "r"(b[0]), "r"(b[1]));
}
// ldmatrix 4x(8x8 b16) transposed
__device__ __forceinline__ void ldmx4t(U32& r0, U32& r1, U32& r2, U32& r3, U32 saddr) {
    asm volatile(
        "ldmatrix.sync.aligned.m8n8.x4.trans.shared.b16 {%0,%1,%2,%3}, [%4];"
        : "=r"(r0), "=r"(r1), "=r"(r2), "=r"(r3) : "r"(saddr));
}

// ---------------------------------------------------------------------------
// Kernel 1: QKV projection, fp16 mma, BK=32, register-prefetch.
// grid=(128,3), 256 thr; CTA 64x128; warps 2x4 (warp tile 32x32).
// Xs: half2 words [64 rows][16 words k] stride 20 (20%32=4 -> A frags cf).
// Ws: fp16 row-major [32 k][128 n] stride 72 words (144B, ldmatrix-phase cf).
// ---------------------------------------------------------------------------
__global__ __launch_bounds__(256) void qkv_h(
    const float* __restrict__ x,
    const float* __restrict__ wq,
    const float* __restrict__ wk,
    const float* __restrict__ wv)
{
    __shared__ U32 Xs[64 * 20];
    __shared__ U32 Ws[32 * 72];

    const int tid = threadIdx.x;
    const int lane = tid & 31;
    const int wid = tid >> 5;
    const int wm = wid >> 2;
    const int wn = wid & 3;
    const int m0 = blockIdx.x * 64;
    const int lr = lane >> 2;
    const int lc = lane & 3;

    const float* w;
    float* o;
    if (blockIdx.y == 0)      { w = wq; o = g_q; }
    else if (blockIdx.y == 1) { w = wk; o = g_k; }
    else                      { w = wv; o = g_v; }

    // ldmatrix per-lane address pieces for B (W) tiles
    const U32 wsb = (U32)__cvta_generic_to_shared(Ws);
    const U32 ldm_row = (U32)((lane & 7) + ((lane >> 3) & 1) * 8);
    const U32 ldm_cb  = (U32)(((lane >> 4) & 1) * 8 * 2);   // byte offset of 8-dim subtile

    const int xr_r = tid >> 3, xr_c = tid & 7;     // X: 2 float4/thr
    const int wr_k = tid >> 5, wr_c = tid & 31;    // W: 4 float4/thr
    float4 xr[2], wr[4];

    #pragma unroll
    for (int i = 0; i < 2; i++)
        xr[i] = *(const float4*)(x + (size_t)(m0 + xr_r + i * 32) * DM + xr_c * 4);
    #pragma unroll
    for (int i = 0; i < 4; i++)
        wr[i] = *(const float4*)(w + (size_t)(wr_k + i * 8) * DH + wr_c * 4);

    float acc[2][4][4];
    #pragma unroll
    for (int mt = 0; mt < 2; mt++)
        #pragma unroll
        for (int nt = 0; nt < 4; nt++)
            #pragma unroll
            for (int j = 0; j < 4; j++) acc[mt][nt][j] = 0.f;

    for (int k0 = 0; k0 < DM; k0 += 32) {
        // commit staged tiles (fp32 -> fp16 here, once)
        #pragma unroll
        for (int i = 0; i < 2; i++)
            *(uint2*)&Xs[(xr_r + i * 32) * 20 + xr_c * 2] =
                make_uint2(f2h2(xr[i].x, xr[i].y), f2h2(xr[i].z, xr[i].w));
        #pragma unroll
        for (int i = 0; i < 4; i++)
            *(uint2*)&Ws[(wr_k + i * 8) * 72 + wr_c * 2] =
                make_uint2(f2h2(wr[i].x, wr[i].y), f2h2(wr[i].z, wr[i].w));
        __syncthreads();

        if (k0 + 32 < DM) {
            #pragma unroll
            for (int i = 0; i < 2; i++)
                xr[i] = *(const float4*)(x + (size_t)(m0 + xr_r + i * 32) * DM + k0 + 32 + xr_c * 4);
            #pragma unroll
            for (int i = 0; i < 4; i++)
                wr[i] = *(const float4*)(w + (size_t)(k0 + 32 + wr_k + i * 8) * DH + wr_c * 4);
        }

        #pragma unroll
        for (int p = 0; p < 2; p++) {              // kstep kb = p*16
            const int kw = p * 8;
            U32 a[2][4];
            #pragma unroll
            for (int mt = 0; mt < 2; mt++) {
                int r = wm * 32 + mt * 16 + lr;
                a[mt][0] = Xs[r * 20 + kw + lc];
                a[mt][1] = Xs[(r + 8) * 20 + kw + lc];
                a[mt][2] = Xs[r * 20 + kw + 4 + lc];
                a[mt][3] = Xs[(r + 8) * 20 + kw + 4 + lc];
            }
            U32 b[4][2];
            #pragma unroll
            for (int p2 = 0; p2 < 2; p2++) {       // 2 ldmatrix -> 4 ntiles
                U32 addr = wsb + ((U32)(p * 16) + ldm_row) * 72 * 4
                         + (U32)(wn * 32 + p2 * 16) * 2 + ldm_cb;
                ldmx4t(b[p2 * 2][0], b[p2 * 2][1], b[p2 * 2 + 1][0], b[p2 * 2 + 1][1], addr);
            }
            #pragma unroll
            for (int mt = 0; mt < 2; mt++)
                #pragma unroll
                for (int nt = 0; nt < 4; nt++)
                    mma16(acc[mt][nt], a[mt], b[nt]);
        }
        __syncthreads();
    }

    #pragma unroll
    for (int mt = 0; mt < 2; mt++)
        #pragma unroll
        for (int nt = 0; nt < 4; nt++) {
            int r = m0 + wm * 32 + mt * 16 + lr;
            int cc = wn * 32 + nt * 8 + 2 * lc;
            *(float2*)(o + (size_t)r * DH + cc) =
                make_float2(acc[mt][nt][0], acc[mt][nt][1]);
            *(float2*)(o + (size_t)(r + 8) * DH + cc) =
                make_float2(acc[mt][nt][2], acc[mt][nt][3]);
        }
}

// ---------------------------------------------------------------------------
// Kernel 2: split-KV causal flash attention, fp16 mma.
// grid=(80,4), 128 thr (4 warps; each owns 16 query rows). LPT chunk order.
// Smem (half2 words): Qs[64][68] Ks[64][68] Vs[64][72] = 53248 B -> 3 CTA/SM.
// P stays in registers (S C-frag == PV A-frag for fp16 k16).
// ---------------------------------------------------------------------------
#define ATTN_SMEM_WORDS (64 * 68 + 64 * 68 + 64 * 72)
#define ATTN_SMEM_BYTES (ATTN_SMEM_WORDS * 4)

__global__ __launch_bounds__(128) void attn_h()
{
    extern __shared__ U32 sm[];
    U32* Qs = sm;                     // stride 68
    U32* Ks = sm + 64 * 68;           // stride 68
    U32* Vs = sm + 2 * 64 * 68;       // stride 72 (fp16 rows, 144B)

    const int tid = threadIdx.x;
    const int lane = tid & 31;
    const int wid = tid >> 5;
    const int lr = lane >> 2;
    const int lc = lane & 3;
    const int b = blockIdx.y;
    const float scale = 0.088388347648318447f;   // 1/sqrt(128)

    const U32 vsb = (U32)__cvta_generic_to_shared(Vs);
    const U32 ldm_row = (U32)((lane & 7) + ((lane >> 3) & 1) * 8);
    const U32 ldm_cb  = (U32)(((lane >> 4) & 1) * 8 * 2);

    // LPT: largest chunks first
    int c = CPB - 1 - blockIdx.x;
    int qt = 0, start = 0;
    for (;;) {
        int n = qt / 8 + 1;
        if (c < start + n) break;
        start += n;
        qt++;
    }
    const int kc = c - start;
    const int kt0 = kc * CHUNK;
    const int kt1 = min(kt0 + CHUNK, qt + 1);
    const int q0 = qt * 64;

    const float* qg = g_q + (size_t)b * SEQ * DH;
    const float* kg = g_k + (size_t)b * SEQ * DH;
    const float* vg = g_v + (size_t)b * SEQ * DH;

    // Q tile (pre-scaled fp16)
    #pragma unroll
    for (int i = 0; i < 16; i++) {
        int idx = tid + i * 128;
        int r = idx >> 5, c4 = idx & 31;
        float4 v = *(const float4*)(qg + (size_t)(q0 + r) * DH + c4 * 4);
        *(uint2*)&Qs[r * 68 + c4 * 2] = make_uint2(
            f2h2(v.x * scale, v.y * scale), f2h2(v.z * scale, v.w * scale));
    }

    float m0v = -1e30f, m1v = -1e30f, l0 = 0.f, l1 = 0.f;
    float O[16][4];
    #pragma unroll
    for (int nt = 0; nt < 16; nt++)
        #pragma unroll
        for (int j = 0; j < 4; j++) O[nt][j] = 0.f;

    const int rloc = wid * 16 + lr;

    for (int t = kt0; t < kt1; t++) {
        const int k0row = t * 64;
        __syncthreads();                  // prev tile's reads of Ks/Vs done (+Q ready)
        #pragma unroll
        for (int i = 0; i < 16; i++) {
            int idx = tid + i * 128;
            int r = idx >> 5, c4 = idx & 31;
            float4 kv = *(const float4*)(kg + (size_t)(k0row + r) * DH + c4 * 4);
            *(uint2*)&Ks[r * 68 + c4 * 2] =
                make_uint2(f2h2(kv.x, kv.y), f2h2(kv.z, kv.w));
            float4 vv = *(const float4*)(vg + (size_t)(k0row + r) * DH + c4 * 4);
            *(uint2*)&Vs[r * 72 + c4 * 2] =
                make_uint2(f2h2(vv.x, vv.y), f2h2(vv.z, vv.w));
        }
        __syncthreads();

        // S = Q @ K^T  (8 ksteps of 16 dims x 8 key ntiles)
        float sc[8][4];
        #pragma unroll
        for (int nt = 0; nt < 8; nt++)
            #pragma unroll
            for (int j = 0; j < 4; j++) sc[nt][j] = 0.f;

        #pragma unroll
        for (int k8 = 0; k8 < 8; k8++) {
            const int kw = k8 * 8;
            U32 a[4];
            a[0] = Qs[rloc * 68 + kw + lc];
            a[1] = Qs[(rloc + 8) * 68 + kw + lc];
            a[2] = Qs[rloc * 68 + kw + 4 + lc];
            a[3] = Qs[(rloc + 8) * 68 + kw + 4 + lc];
            #pragma unroll
            for (int nt = 0; nt < 8; nt++) {
                U32 bb[2];
                int n = nt * 8 + lr;
                bb[0] = Ks[n * 68 + kw + lc];
                bb[1] = Ks[n * 68 + kw + 4 + lc];
                mma16(sc[nt], a, bb);
            }
        }

        if (t == qt) {                    // diagonal tile: causal mask
            #pragma unroll
            for (int nt = 0; nt < 8; nt++) {
                int c0 = nt * 8 + 2 * lc;
                if (c0 > rloc)         sc[nt][0] = -1e30f;
                if (c0 + 1 > rloc)     sc[nt][1] = -1e30f;
                if (c0 > rloc + 8)     sc[nt][2] = -1e30f;
                if (c0 + 1 > rloc + 8) sc[nt][3] = -1e30f;
            }
        }

        // online softmax (rows rloc, rloc+8)
        float mx0 = -1e30f, mx1 = -1e30f;
        #pragma unroll
        for (int nt = 0; nt < 8; nt++) {
            mx0 = fmaxf(mx0, fmaxf(sc[nt][0], sc[nt][1]));
            mx1 = fmaxf(mx1, fmaxf(sc[nt][2], sc[nt][3]));
        }
        mx0 = fmaxf(mx0, __shfl_xor_sync(0xffffffffu, mx0, 1));
        mx0 = fmaxf(mx0, __shfl_xor_sync(0xffffffffu, mx0, 2));
        mx1 = fmaxf(mx1, __shfl_xor_sync(0xffffffffu, mx1, 1));
        mx1 = fmaxf(mx1, __shfl_xor_sync(0xffffffffu, mx1, 2));

        float mn0 = fmaxf(m0v, mx0), mn1 = fmaxf(m1v, mx1);
        float cr0 = __expf(m0v - mn0), cr1 = __expf(m1v - mn1);
        m0v = mn0; m1v = mn1;

        float s0 = 0.f, s1 = 0.f;
        #pragma unroll
        for (int nt = 0; nt < 8; nt++) {
            sc[nt][0] = __expf(sc[nt][0] - mn0);
            sc[nt][1] = __expf(sc[nt][1] - mn0);
            sc[nt][2] = __expf(sc[nt][2] - mn1);
            sc[nt][3] = __expf(sc[nt][3] - mn1);
            s0 += sc[nt][0] + sc[nt][1];
            s1 += sc[nt][2] + sc[nt][3];
        }
        s0 += __shfl_xor_sync(0xffffffffu, s0, 1);
        s0 += __shfl_xor_sync(0xffffffffu, s0, 2);
        s1 += __shfl_xor_sync(0xffffffffu, s1, 1);
        s1 += __shfl_xor_sync(0xffffffffu, s1, 2);
        l0 = l0 * cr0 + s0;
        l1 = l1 * cr1 + s1;

        #pragma unroll
        for (int nt = 0; nt < 16; nt++) {
            O[nt][0] *= cr0; O[nt][1] *= cr0;
            O[nt][2] *= cr1; O[nt][3] *= cr1;
        }

        // O += P @ V : P A-frags = packed S C-frags (no smem round-trip)
        #pragma unroll
        for (int g = 0; g < 4; g++) {     // 16 keys per group
            U32 a[4];
            a[0] = f2h2(sc[2 * g][0],     sc[2 * g][1]);
            a[1] = f2h2(sc[2 * g][2],     sc[2 * g][3]);
            a[2] = f2h2(sc[2 * g + 1][0], sc[2 * g + 1][1]);
            a[3] = f2h2(sc[2 * g + 1][2], sc[2 * g + 1][3]);
            const U32 rowb = vsb + ((U32)(g * 16) + ldm_row) * 72 * 4 + ldm_cb;
            #pragma unroll
            for (int np = 0; np < 8; np++) {      // 8 ldmatrix -> 16 dim-ntiles
                U32 b0, b1, b2, b3;
                ldmx4t(b0, b1, b2, b3, rowb + (U32)(np * 32));
                U32 bA[2] = {b0, b1}, bB[2] = {b2, b3};
                mma16(O[2 * np], a, bA);
                mma16(O[2 * np + 1], a, bB);
            }
        }
    }

    // write partials (unnormalized O, plus m, l)
    const size_t pbase = (size_t)((b * NQT + qt) * 4 + kc);
    float* pO = g_pO + pbase * 64 * DH;
    #pragma unroll
    for (int nt = 0; nt < 16; nt++) {
        int cc = nt * 8 + 2 * lc;
        *(float2*)&pO[rloc * DH + cc]       = make_float2(O[nt][0], O[nt][1]);
        *(float2*)&pO[(rloc + 8) * DH + cc] = make_float2(O[nt][2], O[nt][3]);
    }
    if (lc == 0) {
        g_pm[pbase * 64 + rloc]     = m0v;
        g_pl[pbase * 64 + rloc]     = l0;
        g_pm[pbase * 64 + rloc + 8] = m1v;
        g_pl[pbase * 64 + rloc + 8] = l1;
    }
}

// ---------------------------------------------------------------------------
// Kernel 2b: combine split-KV partials -> g_ctx. grid=(32,4), 256 thr.
// ---------------------------------------------------------------------------
__global__ __launch_bounds__(256) void attn_combine()
{
    const int qt = blockIdx.x, b = blockIdx.y;
    const int nc = qt / 8 + 1;
    const int row = threadIdx.x >> 2;
    const int cs = (threadIdx.x & 3) * 32;
    const size_t pb = (size_t)(b * NQT + qt) * 4;

    float m[4], l[4], w[4];
    float M = -1e30f;
    #pragma unroll 4
    for (int i = 0; i < nc; i++) {
        m[i] = g_pm[(pb + i) * 64 + row];
        l[i] = g_pl[(pb + i) * 64 + row];
        M = fmaxf(M, m[i]);
    }
    float L = 0.f;
    #pragma unroll 4
    for (int i = 0; i < nc; i++) {
        w[i] = __expf(m[i] - M);
        L += w[i] * l[i];
    }
    const float inv = 1.f / L;

    float acc[32];
    #pragma unroll
    for (int j = 0; j < 32; j++) acc[j] = 0.f;

    #pragma unroll 4
    for (int i = 0; i < nc; i++) {
        const float* p = g_pO + (pb + i) * 64 * DH + (size_t)row * DH + cs;
        float wi = w[i];
        #pragma unroll
        for (int j = 0; j < 8; j++) {
            float4 v = *(const float4*)(p + j * 4);
            acc[j * 4 + 0] += wi * v.x;
            acc[j * 4 + 1] += wi * v.y;
            acc[j * 4 + 2] += wi * v.z;
            acc[j * 4 + 3] += wi * v.w;
        }
    }

    float* cg = g_ctx + ((size_t)b * SEQ + qt * 64 + row) * DH + cs;
    #pragma unroll
    for (int j = 0; j < 8; j++)
        *(float4*)(cg + j * 4) = make_float4(acc[j * 4] * inv, acc[j * 4 + 1] * inv,
                                             acc[j * 4 + 2] * inv, acc[j * 4 + 3] * inv);
}

// ---------------------------------------------------------------------------
// Kernel 3: output projection, fp16 mma, BK=32 (4 chunks), register prefetch.
// grid=(128,8), 256 thr; CTA 64x128.
// ---------------------------------------------------------------------------
__global__ __launch_bounds__(256) void proj_h(
    const float* __restrict__ wo, float* __restrict__ out)
{
    __shared__ U32 Xs[64 * 20];
    __shared__ U32 Ws[32 * 72];

    const int tid = threadIdx.x;
    const int lane = tid & 31;
    const int wid = tid >> 5;
    const int wm = wid >> 2;
    const int wn = wid & 3;
    const int m0 = blockIdx.x * 64;
    const int n0 = blockIdx.y * 128;
    const int lr = lane >> 2;
    const int lc = lane & 3;

    const U32 wsb = (U32)__cvta_generic_to_shared(Ws);
    const U32 ldm_row = (U32)((lane & 7) + ((lane >> 3) & 1) * 8);
    const U32 ldm_cb  = (U32)(((lane >> 4) & 1) * 8 * 2);

    const int xr_r = tid >> 3, xr_c = tid & 7;
    const int wr_k = tid >> 5, wr_c = tid & 31;
    float4 xr[2], wr[4];

    #pragma unroll
    for (int i = 0; i < 2; i++)
        xr[i] = *(const float4*)(g_ctx + (size_t)(m0 + xr_r + i * 32) * DH + xr_c * 4);
    #pragma unroll
    for (int i = 0; i < 4; i++)
        wr[i] = *(const float4*)(wo + (size_t)(wr_k + i * 8) * DM + n0 + wr_c * 4);

    float acc[2][4][4];
    #pragma unroll
    for (int mt = 0; mt < 2; mt++)
        #pragma unroll
        for (int nt = 0; nt < 4; nt++)
            #pragma unroll
            for (int j = 0; j < 4; j++) acc[mt][nt][j] = 0.f;

    for (int k0 = 0; k0 < DH; k0 += 32) {
        #pragma unroll
        for (int i = 0; i < 2; i++)
            *(uint2*)&Xs[(xr_r + i * 32) * 20 + xr_c * 2] =
                make_uint2(f2h2(xr[i].x, xr[i].y), f2h2(xr[i].z, xr[i].w));
        #pragma unroll
        for (int i = 0; i < 4; i++)
            *(uint2*)&Ws[(wr_k + i * 8) * 72 + wr_c * 2] =
                make_uint2(f2h2(wr[i].x, wr[i].y), f2h2(wr[i].z, wr[i].w));
        __syncthreads();

        if (k0 + 32 < DH) {
            #pragma unroll
            for (int i = 0; i < 2; i++)
                xr[i] = *(const float4*)(g_ctx + (size_t)(m0 + xr_r + i * 32) * DH + k0 + 32 + xr_c * 4);
            #pragma unroll
            for (int i = 0; i < 4; i++)
                wr[i] = *(const float4*)(wo + (size_t)(k0 + 32 + wr_k + i * 8) * DM + n0 + wr_c * 4);
        }

        #pragma unroll
        for (int p = 0; p < 2; p++) {
            const int kw = p * 8;
            U32 a[2][4];
            #pragma unroll
            for (int mt = 0; mt < 2; mt++) {
                int r = wm * 32 + mt * 16 + lr;
                a[mt][0] = Xs[r * 20 + kw + lc];
                a[mt][1] = Xs[(r + 8) * 20 + kw + lc];
                a[mt][2] = Xs[r * 20 + kw + 4 + lc];
                a[mt][3] = Xs[(r + 8) * 20 + kw + 4 + lc];
            }
            U32 b[4][2];
            #pragma unroll
            for (int p2 = 0; p2 < 2; p2++) {
                U32 addr = wsb + ((U32)(p * 16) + ldm_row) * 72 * 4
                         + (U32)(wn * 32 + p2 * 16) * 2 + ldm_cb;
                ldmx4t(b[p2 * 2][0], b[p2 * 2][1], b[p2 * 2 + 1][0], b[p2 * 2 + 1][1], addr);
            }
            #pragma unroll
            for (int mt = 0; mt < 2; mt++)
                #pragma unroll
                for (int nt = 0; nt < 4; nt++)
                    mma16(acc[mt][nt], a[mt], b[nt]);
        }
        __syncthreads();
    }

    #pragma unroll
    for (int mt = 0; mt < 2; mt++)
        #pragma unroll
        for (int nt = 0; nt < 4; nt++) {
            int r = m0 + wm * 32 + mt * 16 + lr;
            int cc = n0 + wn * 32 + nt * 8 + 2 * lc;
            *(float2*)(out + (size_t)r * DM + cc) =
                make_float2(acc[mt][nt][0], acc[mt][nt][1]);
            *(float2*)(out + (size_t)(r + 8) * DM + cc) =
                make_float2(acc[mt][nt][2], acc[mt][nt][3]);
        }
}

// ---------------------------------------------------------------------------
extern "C" void kernel_launch(void* const* d_in, const int* in_sizes, int n_in,
                              void* d_out, int out_size)
{
    const float* x  = (const float*)d_in[0];
    const float* wq = (const float*)d_in[1];
    const float* wk = (const float*)d_in[2];
    const float* wv = (const float*)d_in[3];
    const float* wo = (const float*)d_in[4];
    float* out = (float*)d_out;
    (void)in_sizes; (void)n_in; (void)out_size;

    qkv_h<<<dim3(NB * SEQ / 64, 3), 256>>>(x, wq, wk, wv);

    cudaFuncSetAttribute(attn_h,
                         cudaFuncAttributeMaxDynamicSharedMemorySize,
                         ATTN_SMEM_BYTES);
    attn_h<<<dim3(CPB, NB), 128, ATTN_SMEM_BYTES>>>();

    attn_combine<<<dim3(NQT, NB), 256>>>();

    proj_h<<<dim3(NB * SEQ / 64, DM / 128), 256>>>(wo, out);
}

// round 13
// speedup vs baseline: 1.5890x; 1.1901x over previous
#include <cuda_runtime.h>
#include <math.h>

#define NB 4
#define SEQ 2048
#define DM 1024
#define DH 128
#define CHUNK 8                 // kv tiles (of 64) per attention CTA
#define NQT (SEQ / 64)          // 32 q-tiles
#define CPB 80                  // chunks per batch = 8*(1+2+3+4)
typedef unsigned int U32;

// fp16 scratch (device globals: allocation-free rule). U32 = half2.
__device__ U32 g_xh[NB * SEQ * DM / 2];
__device__ U32 g_wqh[DM * DH / 2];
__device__ U32 g_wkh[DM * DH / 2];
__device__ U32 g_wvh[DM * DH / 2];
__device__ U32 g_woh[DH * DM / 2];
__device__ U32 g_qh[NB * SEQ * DH / 2];   // pre-scaled by 1/sqrt(dh)
__device__ U32 g_kh[NB * SEQ * DH / 2];
__device__ U32 g_vh[NB * SEQ * DH / 2];
__device__ U32 g_ctxh[NB * SEQ * DH / 2];
// split-KV partials (fp32)
__device__ float g_pO[NB * NQT * 4 * 64 * DH];
__device__ float g_pm[NB * NQT * 4 * 64];
__device__ float g_pl[NB * NQT * 4 * 64];

// ---------------------------------------------------------------------------
// helpers
// ---------------------------------------------------------------------------
__device__ __forceinline__ U32 f2h2(float lo, float hi) {
    U32 u;
    asm("cvt.rn.f16x2.f32 %0, %1, %2;" : "=r"(u) : "f"(hi), "f"(lo));
    return u;
}
__device__ __forceinline__ void mma16(float* c, const U32* a, const U32* b) {
    asm volatile(
        "mma.sync.aligned.m16n8k16.row.col.f32.f16.f16.f32 "
        "{%0,%1,%2,%3}, {%4,%5,%6,%7}, {%8,%9}, {%0,%1,%2,%3};\n"
        : "+f"(c[0]), "+f"(c[1]), "+f"(c[2]), "+f"(c[3])
        : "r"(a[0]), "r"(a[1]), "r"(a[2]), "r"(a[3]),
          "r"(b[0]), "r"(b[1]));
}
__device__ __forceinline__ void ldmx4(U32& r0, U32& r1, U32& r2, U32& r3, U32 saddr) {
    asm volatile(
        "ldmatrix.sync.aligned.m8n8.x4.shared.b16 {%0,%1,%2,%3}, [%4];"
        : "=r"(r0), "=r"(r1), "=r"(r2), "=r"(r3) : "r"(saddr));
}
__device__ __forceinline__ void ldmx4t(U32& r0, U32& r1, U32& r2, U32& r3, U32 saddr) {
    asm volatile(
        "ldmatrix.sync.aligned.m8n8.x4.trans.shared.b16 {%0,%1,%2,%3}, [%4];"
        : "=r"(r0), "=r"(r1), "=r"(r2), "=r"(r3) : "r"(saddr));
}
__device__ __forceinline__ void cpa(U32 saddr, const U32* g) {
    asm volatile("cp.async.ca.shared.global [%0], [%1], 16;\n"
                 :: "r"(saddr), "l"(g));
}
#define CP_COMMIT asm volatile("cp.async.commit_group;\n" ::: "memory")
#define CP_WAIT(n) asm volatile("cp.async.wait_group %0;\n" :: "n"(n) : "memory")

// ---------------------------------------------------------------------------
// Kernel 0: fp32 -> fp16 conversion of x and all weights. 8704 blocks x 256.
// ---------------------------------------------------------------------------
#define X4 (NB * SEQ * DM / 4)
#define W4 (DM * DH / 4)
__global__ __launch_bounds__(256) void cvt_all(
    const float* __restrict__ x,  const float* __restrict__ wq,
    const float* __restrict__ wk, const float* __restrict__ wv,
    const float* __restrict__ wo)
{
    int idx = blockIdx.x * 256 + threadIdx.x;
    const float4* src;
    U32* dst;
    if (idx < X4)               { src = (const float4*)x  + idx;             dst = g_xh  + (size_t)idx * 2; }
    else if (idx < X4 + W4)     { int j = idx - X4;         src = (const float4*)wq + j; dst = g_wqh + (size_t)j * 2; }
    else if (idx < X4 + 2 * W4) { int j = idx - X4 - W4;    src = (const float4*)wk + j; dst = g_wkh + (size_t)j * 2; }
    else if (idx < X4 + 3 * W4) { int j = idx - X4 - 2 * W4; src = (const float4*)wv + j; dst = g_wvh + (size_t)j * 2; }
    else                        { int j = idx - X4 - 3 * W4; src = (const float4*)wo + j; dst = g_woh + (size_t)j * 2; }
    float4 v = *src;
    dst[0] = f2h2(v.x, v.y);
    dst[1] = f2h2(v.z, v.w);
}

// ---------------------------------------------------------------------------
// fp16 tensor-core GEMM core: CTA tile 128x128, 128 thr (4 warps, 2x2 grid,
// warp tile 64x64), BK=32, cp.async 2-stage double buffer, no cvt in loop.
// Smem per stage (U32 words): Xs[128 rows][20] (16 data + 4 pad),
//                             Ws[32 k][68] (64 data + 4 pad).  2 stages.
// Both padded strides give the conflict-free 4r / 20r bank patterns for
// ldmatrix(A, non-trans) and ldmatrix(B, trans).
// ---------------------------------------------------------------------------
#define GST (128 * 20 + 32 * 68)           // words per stage = 4736
#define G_SMEM_WORDS (2 * GST)

#define G_ISSUE(s, k0) do {                                                   \
    U32 base_ = sb + (U32)((s) * GST * 4);                                    \
    _Pragma("unroll")                                                         \
    for (int i_ = 0; i_ < 4; i_++) {                                          \
        int idx_ = tid + i_ * 128;                                            \
        int r_ = idx_ >> 2, c_ = idx_ & 3;                                    \
        cpa(base_ + (U32)(r_ * 20 + c_ * 4) * 4,                              \
            Ah + (size_t)(m0 + r_) * sAw + ((k0) >> 1) + c_ * 4);             \
    }                                                                         \
    _Pragma("unroll")                                                         \
    for (int i_ = 0; i_ < 4; i_++) {                                          \
        int idx_ = tid + i_ * 128;                                            \
        int k_ = idx_ >> 4, c_ = idx_ & 15;                                   \
        cpa(base_ + (U32)(128 * 20 + k_ * 68 + c_ * 4) * 4,                   \
            Bh + (size_t)((k0) + k_) * sBw + n0w + c_ * 4);                   \
    }                                                                         \
} while (0)

__device__ __forceinline__ void gemm_core(
    U32 sb, const U32* Ah, int sAw, const U32* Bh, int sBw,
    int m0, int n0w, int nstages, float acc[4][8][4])
{
    const int tid = threadIdx.x;
    const int lane = tid & 31;
    const int wid = tid >> 5;
    const int wm = wid >> 1, wn = wid & 1;
    const U32 ldmr = (U32)((lane & 7) + ((lane >> 3) & 1) * 8);
    const U32 hi = (U32)((lane >> 4) & 1);

    G_ISSUE(0, 0);
    CP_COMMIT;

    for (int i = 0; i < nstages; i++) {
        CP_WAIT(0);
        __syncthreads();
        if (i + 1 < nstages) {
            G_ISSUE((i + 1) & 1, (i + 1) * 32);
            CP_COMMIT;
        }
        const U32 st = sb + (U32)((i & 1) * GST * 4);

        #pragma unroll
        for (int p = 0; p < 2; p++) {
            U32 a[4][4];
            #pragma unroll
            for (int mt = 0; mt < 4; mt++)
                ldmx4(a[mt][0], a[mt][1], a[mt][2], a[mt][3],
                      st + (U32)(((wm * 64 + mt * 16) + ldmr) * 20 + p * 8 + hi * 4) * 4);
            U32 b[8][2];
            #pragma unroll
            for (int nb = 0; nb < 4; nb++)
                ldmx4t(b[nb * 2][0], b[nb * 2][1], b[nb * 2 + 1][0], b[nb * 2 + 1][1],
                       st + (U32)(128 * 20 + (p * 16 + ldmr) * 68
                                  + wn * 32 + nb * 8 + hi * 4) * 4);
            #pragma unroll
            for (int mt = 0; mt < 4; mt++)
                #pragma unroll
                for (int nt = 0; nt < 8; nt++)
                    mma16(acc[mt][nt], a[mt], b[nt]);
        }
    }
}

// ---------------------------------------------------------------------------
// Kernel 1: QKV projection. grid=(64,3), 128 thr. Writes fp16 q(scaled)/k/v.
// ---------------------------------------------------------------------------
__global__ __launch_bounds__(128) void qkv_h(int dummy)
{
    __shared__ U32 gsm[G_SMEM_WORDS];
    const U32 sb = (U32)__cvta_generic_to_shared(gsm);
    const int tid = threadIdx.x;
    const int lane = tid & 31;
    const int wid = tid >> 5;
    const int wm = wid >> 1, wn = wid & 1;
    const int lr = lane >> 2, lc = lane & 3;
    const int m0 = blockIdx.x * 128;

    const U32* Bh;
    U32* oh;
    float s;
    if (blockIdx.y == 0)      { Bh = g_wqh; oh = g_qh; s = 0.088388347648318447f; }
    else if (blockIdx.y == 1) { Bh = g_wkh; oh = g_kh; s = 1.f; }
    else                      { Bh = g_wvh; oh = g_vh; s = 1.f; }

    float acc[4][8][4];
    #pragma unroll
    for (int mt = 0; mt < 4; mt++)
        #pragma unroll
        for (int nt = 0; nt < 8; nt++)
            #pragma unroll
            for (int j = 0; j < 4; j++) acc[mt][nt][j] = 0.f;

    gemm_core(sb, g_xh, DM / 2, Bh, DH / 2, m0, 0, DM / 32, acc);

    #pragma unroll
    for (int mt = 0; mt < 4; mt++)
        #pragma unroll
        for (int nt = 0; nt < 8; nt++) {
            int row = m0 + wm * 64 + mt * 16 + lr;
            int cw = wn * 32 + nt * 4 + lc;
            oh[(size_t)row * 64 + cw]       = f2h2(acc[mt][nt][0] * s, acc[mt][nt][1] * s);
            oh[(size_t)(row + 8) * 64 + cw] = f2h2(acc[mt][nt][2] * s, acc[mt][nt][3] * s);
        }
    (void)dummy;
}

// ---------------------------------------------------------------------------
// Kernel 3: output projection. grid=(64,8), 128 thr. fp32 out.
// ---------------------------------------------------------------------------
__global__ __launch_bounds__(128) void proj_h(float* __restrict__ out)
{
    __shared__ U32 gsm[G_SMEM_WORDS];
    const U32 sb = (U32)__cvta_generic_to_shared(gsm);
    const int tid = threadIdx.x;
    const int lane = tid & 31;
    const int wid = tid >> 5;
    const int wm = wid >> 1, wn = wid & 1;
    const int lr = lane >> 2, lc = lane & 3;
    const int m0 = blockIdx.x * 128;
    const int n0 = blockIdx.y * 128;

    float acc[4][8][4];
    #pragma unroll
    for (int mt = 0; mt < 4; mt++)
        #pragma unroll
        for (int nt = 0; nt < 8; nt++)
            #pragma unroll
            for (int j = 0; j < 4; j++) acc[mt][nt][j] = 0.f;

    gemm_core(sb, g_ctxh, DH / 2, g_woh, DM / 2, m0, n0 / 2, DH / 32, acc);

    #pragma unroll
    for (int mt = 0; mt < 4; mt++)
        #pragma unroll
        for (int nt = 0; nt < 8; nt++) {
            int row = m0 + wm * 64 + mt * 16 + lr;
            int col = n0 + wn * 64 + nt * 8 + 2 * lc;
            *(float2*)(out + (size_t)row * DM + col) =
                make_float2(acc[mt][nt][0], acc[mt][nt][1]);
            *(float2*)(out + (size_t)(row + 8) * DM + col) =
                make_float2(acc[mt][nt][2], acc[mt][nt][3]);
        }
}

// ---------------------------------------------------------------------------
// Kernel 2: split-KV causal flash attention, fp16 mma, fp16 gmem operands.
// grid=(80,4), 128 thr. Smem: Qs/Ks/Vs all stride 68 words = 52224 B.
// ---------------------------------------------------------------------------
#define ATTN_SMEM_WORDS (3 * 64 * 68)
#define ATTN_SMEM_BYTES (ATTN_SMEM_WORDS * 4)

__global__ __launch_bounds__(128) void attn_h()
{
    extern __shared__ U32 sm[];
    U32* Qs = sm;                     // stride 68
    U32* Ks = sm + 64 * 68;           // stride 68
    U32* Vs = sm + 2 * 64 * 68;       // stride 68 (conflict-free ldmatrix)

    const int tid = threadIdx.x;
    const int lane = tid & 31;
    const int wid = tid >> 5;
    const int lr = lane >> 2;
    const int lc = lane & 3;
    const int b = blockIdx.y;

    const U32 vsb = (U32)__cvta_generic_to_shared(Vs);
    const U32 ldm_row = (U32)((lane & 7) + ((lane >> 3) & 1) * 8);
    const U32 ldm_cb  = (U32)(((lane >> 4) & 1) * 16);

    // LPT: largest chunks first
    int c = CPB - 1 - blockIdx.x;
    int qt = 0, start = 0;
    for (;;) {
        int n = qt / 8 + 1;
        if (c < start + n) break;
        start += n;
        qt++;
    }
    const int kc = c - start;
    const int kt0 = kc * CHUNK;
    const int kt1 = min(kt0 + CHUNK, qt + 1);
    const int q0 = qt * 64;

    const U32* qh = g_qh + (size_t)b * SEQ * 64;
    const U32* kh = g_kh + (size_t)b * SEQ * 64;
    const U32* vh = g_vh + (size_t)b * SEQ * 64;

    // Q tile (already fp16 + scaled): 8 uint4/thr
    #pragma unroll
    for (int i = 0; i < 8; i++) {
        int idx = tid + i * 128;
        int r = idx >> 4, cc = idx & 15;
        *(uint4*)&Qs[r * 68 + cc * 4] = *(const uint4*)(qh + (size_t)(q0 + r) * 64 + cc * 4);
    }

    float m0v = -1e30f, m1v = -1e30f, l0 = 0.f, l1 = 0.f;
    float O[16][4];
    #pragma unroll
    for (int nt = 0; nt < 16; nt++)
        #pragma unroll
        for (int j = 0; j < 4; j++) O[nt][j] = 0.f;

    const int rloc = wid * 16 + lr;

    for (int t = kt0; t < kt1; t++) {
        const int k0row = t * 64;
        __syncthreads();
        #pragma unroll
        for (int i = 0; i < 8; i++) {
            int idx = tid + i * 128;
            int r = idx >> 4, cc = idx & 15;
            *(uint4*)&Ks[r * 68 + cc * 4] = *(const uint4*)(kh + (size_t)(k0row + r) * 64 + cc * 4);
            *(uint4*)&Vs[r * 68 + cc * 4] = *(const uint4*)(vh + (size_t)(k0row + r) * 64 + cc * 4);
        }
        __syncthreads();

        // S = Q @ K^T
        float sc[8][4];
        #pragma unroll
        for (int nt = 0; nt < 8; nt++)
            #pragma unroll
            for (int j = 0; j < 4; j++) sc[nt][j] = 0.f;

        #pragma unroll
        for (int k8 = 0; k8 < 8; k8++) {
            const int kw = k8 * 8;
            U32 a[4];
            a[0] = Qs[rloc * 68 + kw + lc];
            a[1] = Qs[(rloc + 8) * 68 + kw + lc];
            a[2] = Qs[rloc * 68 + kw + 4 + lc];
            a[3] = Qs[(rloc + 8) * 68 + kw + 4 + lc];
            #pragma unroll
            for (int nt = 0; nt < 8; nt++) {
                U32 bb[2];
                int n = nt * 8 + lr;
                bb[0] = Ks[n * 68 + kw + lc];
                bb[1] = Ks[n * 68 + kw + 4 + lc];
                mma16(sc[nt], a, bb);
            }
        }

        if (t == qt) {                    // diagonal tile: causal mask
            #pragma unroll
            for (int nt = 0; nt < 8; nt++) {
                int c0 = nt * 8 + 2 * lc;
                if (c0 > rloc)         sc[nt][0] = -1e30f;
                if (c0 + 1 > rloc)     sc[nt][1] = -1e30f;
                if (c0 > rloc + 8)     sc[nt][2] = -1e30f;
                if (c0 + 1 > rloc + 8) sc[nt][3] = -1e30f;
            }
        }

        // online softmax (rows rloc, rloc+8)
        float mx0 = -1e30f, mx1 = -1e30f;
        #pragma unroll
        for (int nt = 0; nt < 8; nt++) {
            mx0 = fmaxf(mx0, fmaxf(sc[nt][0], sc[nt][1]));
            mx1 = fmaxf(mx1, fmaxf(sc[nt][2], sc[nt][3]));
        }
        mx0 = fmaxf(mx0, __shfl_xor_sync(0xffffffffu, mx0, 1));
        mx0 = fmaxf(mx0, __shfl_xor_sync(0xffffffffu, mx0, 2));
        mx1 = fmaxf(mx1, __shfl_xor_sync(0xffffffffu, mx1, 1));
        mx1 = fmaxf(mx1, __shfl_xor_sync(0xffffffffu, mx1, 2));

        float mn0 = fmaxf(m0v, mx0), mn1 = fmaxf(m1v, mx1);
        float cr0 = __expf(m0v - mn0), cr1 = __expf(m1v - mn1);
        m0v = mn0; m1v = mn1;

        float s0 = 0.f, s1 = 0.f;
        #pragma unroll
        for (int nt = 0; nt < 8; nt++) {
            sc[nt][0] = __expf(sc[nt][0] - mn0);
            sc[nt][1] = __expf(sc[nt][1] - mn0);
            sc[nt][2] = __expf(sc[nt][2] - mn1);
            sc[nt][3] = __expf(sc[nt][3] - mn1);
            s0 += sc[nt][0] + sc[nt][1];
            s1 += sc[nt][2] + sc[nt][3];
        }
        s0 += __shfl_xor_sync(0xffffffffu, s0, 1);
        s0 += __shfl_xor_sync(0xffffffffu, s0, 2);
        s1 += __shfl_xor_sync(0xffffffffu, s1, 1);
        s1 += __shfl_xor_sync(0xffffffffu, s1, 2);
        l0 = l0 * cr0 + s0;
        l1 = l1 * cr1 + s1;

        #pragma unroll
        for (int nt = 0; nt < 16; nt++) {
            O[nt][0] *= cr0; O[nt][1] *= cr0;
            O[nt][2] *= cr1; O[nt][3] *= cr1;
        }

        // O += P @ V : P A-frags packed from S C-frags (no smem round-trip)
        #pragma unroll
        for (int g = 0; g < 4; g++) {
            U32 a[4];
            a[0] = f2h2(sc[2 * g][0],     sc[2 * g][1]);
            a[1] = f2h2(sc[2 * g][2],     sc[2 * g][3]);
            a[2] = f2h2(sc[2 * g + 1][0], sc[2 * g + 1][1]);
            a[3] = f2h2(sc[2 * g + 1][2], sc[2 * g + 1][3]);
            const U32 rowb = vsb + ((U32)(g * 16) + ldm_row) * 68 * 4 + ldm_cb;
            #pragma unroll
            for (int np = 0; np < 8; np++) {
                U32 b0, b1, b2, b3;
                ldmx4t(b0, b1, b2, b3, rowb + (U32)(np * 32));
                U32 bA[2] = {b0, b1}, bB[2] = {b2, b3};
                mma16(O[2 * np], a, bA);
                mma16(O[2 * np + 1], a, bB);
            }
        }
    }

    // write partials (unnormalized O, plus m, l)
    const size_t pbase = (size_t)((b * NQT + qt) * 4 + kc);
    float* pO = g_pO + pbase * 64 * DH;
    #pragma unroll
    for (int nt = 0; nt < 16; nt++) {
        int cc = nt * 8 + 2 * lc;
        *(float2*)&pO[rloc * DH + cc]       = make_float2(O[nt][0], O[nt][1]);
        *(float2*)&pO[(rloc + 8) * DH + cc] = make_float2(O[nt][2], O[nt][3]);
    }
    if (lc == 0) {
        g_pm[pbase * 64 + rloc]     = m0v;
        g_pl[pbase * 64 + rloc]     = l0;
        g_pm[pbase * 64 + rloc + 8] = m1v;
        g_pl[pbase * 64 + rloc + 8] = l1;
    }
}

// ---------------------------------------------------------------------------
// Kernel 2b: combine split-KV partials -> g_ctxh (fp16). grid=(32,4), 256 thr.
// ---------------------------------------------------------------------------
__global__ __launch_bounds__(256) void attn_combine()
{
    const int qt = blockIdx.x, b = blockIdx.y;
    const int nc = qt / 8 + 1;
    const int row = threadIdx.x >> 2;
    const int cs = (threadIdx.x & 3) * 32;
    const size_t pb = (size_t)(b * NQT + qt) * 4;

    float m[4], l[4], w[4];
    float M = -1e30f;
    #pragma unroll 4
    for (int i = 0; i < nc; i++) {
        m[i] = g_pm[(pb + i) * 64 + row];
        l[i] = g_pl[(pb + i) * 64 + row];
        M = fmaxf(M, m[i]);
    }
    float L = 0.f;
    #pragma unroll 4
    for (int i = 0; i < nc; i++) {
        w[i] = __expf(m[i] - M);
        L += w[i] * l[i];
    }
    const float inv = 1.f / L;

    float acc[32];
    #pragma unroll
    for (int j = 0; j < 32; j++) acc[j] = 0.f;

    #pragma unroll 4
    for (int i = 0; i < nc; i++) {
        const float* p = g_pO + (pb + i) * 64 * DH + (size_t)row * DH + cs;
        float wi = w[i];
        #pragma unroll
        for (int j = 0; j < 8; j++) {
            float4 v = *(const float4*)(p + j * 4);
            acc[j * 4 + 0] += wi * v.x;
            acc[j * 4 + 1] += wi * v.y;
            acc[j * 4 + 2] += wi * v.z;
            acc[j * 4 + 3] += wi * v.w;
        }
    }

    U32* cg = g_ctxh + ((size_t)b * SEQ + qt * 64 + row) * 64 + (cs >> 1);
    #pragma unroll
    for (int j = 0; j < 16; j++)
        cg[j] = f2h2(acc[2 * j] * inv, acc[2 * j + 1] * inv);
}

// ---------------------------------------------------------------------------
extern "C" void kernel_launch(void* const* d_in, const int* in_sizes, int n_in,
                              void* d_out, int out_size)
{
    const float* x  = (const float*)d_in[0];
    const float* wq = (const float*)d_in[1];
    const float* wk = (const float*)d_in[2];
    const float* wv = (const float*)d_in[3];
    const float* wo = (const float*)d_in[4];
    float* out = (float*)d_out;
    (void)in_sizes; (void)n_in; (void)out_size;

    cvt_all<<<(X4 + 4 * W4) / 256, 256>>>(x, wq, wk, wv, wo);

    qkv_h<<<dim3(NB * SEQ / 128, 3), 128>>>(0);

    cudaFuncSetAttribute(attn_h,
                         cudaFuncAttributeMaxDynamicSharedMemorySize,
                         ATTN_SMEM_BYTES);
    attn_h<<<dim3(CPB, NB), 128, ATTN_SMEM_BYTES>>>();

    attn_combine<<<dim3(NQT, NB), 256>>>();

    proj_h<<<dim3(NB * SEQ / 128, DM / 128), 128>>>(out);
}